// round 2
// baseline (speedup 1.0000x reference)
#include <cuda_runtime.h>
#include <cstdint>

// Problem constants (fixed shapes for this problem instance).
#define NMAX   100000
#define EMAX   1600000
#define INDIM  512
#define HID    64
#define NCLS   16

// ---------------- scratch (device globals; no allocation allowed) ----------
__device__ __align__(256) float g_dis [NMAX];                    // deg -> rsqrt(deg), in place
__device__ __align__(256) float g_norm[EMAX];                    // per-edge norm
__device__ __align__(256) float g_H  [(size_t)NMAX * HID];       // x @ W1
__device__ __align__(256) float g_O1 [(size_t)NMAX * HID];       // aggregated layer-1 (pre b1/relu)
__device__ __align__(256) float g_H2 [(size_t)NMAX * NCLS];      // relu(O1+b1) @ W2
__device__ __align__(256) float g_O2 [(size_t)NMAX * NCLS];      // aggregated layer-2 (pre b2)

// ---------------- degree / normalization ----------------------------------
__global__ void k_deg_init(int n) {
    int i = blockIdx.x * blockDim.x + threadIdx.x;
    if (i < n) g_dis[i] = 1.0f;                 // self-loop weight
}

__global__ void k_deg_acc(const int* __restrict__ dst, const float* __restrict__ w, int E) {
    int e = blockIdx.x * blockDim.x + threadIdx.x;
    if (e < E) atomicAdd(&g_dis[dst[e]], w[e]);
}

__global__ void k_deg_fin(int n) {
    int i = blockIdx.x * blockDim.x + threadIdx.x;
    if (i < n) g_dis[i] = rsqrtf(g_dis[i]);     // deg >= 1 always (self loop)
}

__global__ void k_norm(const int* __restrict__ src, const int* __restrict__ dst,
                       const float* __restrict__ w, int E) {
    int e = blockIdx.x * blockDim.x + threadIdx.x;
    if (e < E) g_norm[e] = g_dis[src[e]] * w[e] * g_dis[dst[e]];
}

// ---------------- GEMM1: H = X @ W1 ; O1 = H * selfnorm --------------------
// BM=128, BN=64(=HID), BK=32, 256 threads, thread tile 8x4.
#define BM 128
#define BN 64
#define BK 32

__global__ __launch_bounds__(256)
void k_gemm1(const float* __restrict__ X, const float* __restrict__ W1, int Nrows) {
    __shared__ float Xs[BK][BM + 4];   // transposed: Xs[k][row]
    __shared__ float Ws[BK][BN];       // Ws[k][col]

    const int tid = threadIdx.x;
    const int rowBase = blockIdx.x * BM;
    const int tx = tid & 15;           // col group: 16 groups * 4 cols
    const int ty = tid >> 4;           // row group: 16 groups * 8 rows

    float acc[8][4];
    #pragma unroll
    for (int i = 0; i < 8; i++)
        #pragma unroll
        for (int j = 0; j < 4; j++) acc[i][j] = 0.0f;

    for (int k0 = 0; k0 < INDIM; k0 += BK) {
        // X tile: 128 rows x 32 k = 1024 float4, 4 per thread
        #pragma unroll
        for (int p = 0; p < 4; p++) {
            int f4 = tid + p * 256;        // 0..1023
            int r  = f4 >> 3;              // row within tile
            int kq = f4 & 7;               // float4 slot within 32 k
            int grow = rowBase + r;
            float4 v = make_float4(0.f, 0.f, 0.f, 0.f);
            if (grow < Nrows)
                v = *(const float4*)&X[(size_t)grow * INDIM + k0 + kq * 4];
            Xs[kq * 4 + 0][r] = v.x;
            Xs[kq * 4 + 1][r] = v.y;
            Xs[kq * 4 + 2][r] = v.z;
            Xs[kq * 4 + 3][r] = v.w;
        }
        // W tile: 32 k x 64 cols = 512 float4, 2 per thread
        #pragma unroll
        for (int p = 0; p < 2; p++) {
            int f4 = tid + p * 256;        // 0..511
            int kk = f4 >> 4;
            int cq = f4 & 15;
            *(float4*)&Ws[kk][cq * 4] =
                *(const float4*)&W1[(size_t)(k0 + kk) * BN + cq * 4];
        }
        __syncthreads();

        #pragma unroll
        for (int k = 0; k < BK; k++) {
            float a[8], b[4];
            *(float4*)&a[0] = *(const float4*)&Xs[k][ty * 8];
            *(float4*)&a[4] = *(const float4*)&Xs[k][ty * 8 + 4];
            *(float4*)&b[0] = *(const float4*)&Ws[k][tx * 4];
            #pragma unroll
            for (int i = 0; i < 8; i++)
                #pragma unroll
                for (int j = 0; j < 4; j++)
                    acc[i][j] += a[i] * b[j];
        }
        __syncthreads();
    }

    // Epilogue: write H and O1 = H * dis^2 (self-loop init of the accumulator)
    #pragma unroll
    for (int i = 0; i < 8; i++) {
        int grow = rowBase + ty * 8 + i;
        if (grow < Nrows) {
            float d  = g_dis[grow];
            float sn = d * d;
            float4 v = make_float4(acc[i][0], acc[i][1], acc[i][2], acc[i][3]);
            *(float4*)&g_H [(size_t)grow * HID + tx * 4] = v;
            float4 o = make_float4(v.x * sn, v.y * sn, v.z * sn, v.w * sn);
            *(float4*)&g_O1[(size_t)grow * HID + tx * 4] = o;
        }
    }
}

// ---------------- edge aggregation, 64 features (half-warp per edge) -------
__device__ __forceinline__ void red_add_v4(float* addr, float a, float b, float c, float d) {
    asm volatile("red.global.add.v4.f32 [%0], {%1, %2, %3, %4};"
                 :: "l"(addr), "f"(a), "f"(b), "f"(c), "f"(d) : "memory");
}

__global__ __launch_bounds__(256)
void k_agg64(const int* __restrict__ src, const int* __restrict__ dst, int E) {
    int t = blockIdx.x * blockDim.x + threadIdx.x;
    int e = t >> 4;
    if (e >= E) return;
    int lane = t & 15;
    int s = src[e];
    int d = dst[e];
    float nr = g_norm[e];
    float4 v = *(const float4*)&g_H[(size_t)s * HID + lane * 4];
    red_add_v4(&g_O1[(size_t)d * HID + lane * 4], v.x * nr, v.y * nr, v.z * nr, v.w * nr);
}

// ---------------- layer 2: H2 = relu(O1+b1) @ W2 ; O2 = H2 * selfnorm ------
__global__ __launch_bounds__(256)
void k_layer2(const float* __restrict__ b1, const float* __restrict__ W2, int Nn) {
    __shared__ float Ws[HID * NCLS];   // 64*16
    __shared__ float bs[HID];
    for (int i = threadIdx.x; i < HID * NCLS; i += blockDim.x) Ws[i] = W2[i];
    if (threadIdx.x < HID) bs[threadIdx.x] = b1[threadIdx.x];
    __syncthreads();

    int n = blockIdx.x * blockDim.x + threadIdx.x;
    if (n >= Nn) return;

    float acc[NCLS];
    #pragma unroll
    for (int c = 0; c < NCLS; c++) acc[c] = 0.0f;

    const float* row = &g_O1[(size_t)n * HID];
    #pragma unroll
    for (int jq = 0; jq < HID / 4; jq++) {
        float4 r = *(const float4*)&row[jq * 4];
        float tv[4];
        tv[0] = fmaxf(r.x + bs[jq * 4 + 0], 0.f);
        tv[1] = fmaxf(r.y + bs[jq * 4 + 1], 0.f);
        tv[2] = fmaxf(r.z + bs[jq * 4 + 2], 0.f);
        tv[3] = fmaxf(r.w + bs[jq * 4 + 3], 0.f);
        #pragma unroll
        for (int u = 0; u < 4; u++) {
            int j = jq * 4 + u;
            float tvu = tv[u];
            #pragma unroll
            for (int cq = 0; cq < 4; cq++) {
                float4 w = *(const float4*)&Ws[j * NCLS + cq * 4];
                acc[cq * 4 + 0] += tvu * w.x;
                acc[cq * 4 + 1] += tvu * w.y;
                acc[cq * 4 + 2] += tvu * w.z;
                acc[cq * 4 + 3] += tvu * w.w;
            }
        }
    }

    float d  = g_dis[n];
    float sn = d * d;
    #pragma unroll
    for (int cq = 0; cq < 4; cq++) {
        float4 v = make_float4(acc[cq*4+0], acc[cq*4+1], acc[cq*4+2], acc[cq*4+3]);
        *(float4*)&g_H2[(size_t)n * NCLS + cq * 4] = v;
        float4 o = make_float4(v.x * sn, v.y * sn, v.z * sn, v.w * sn);
        *(float4*)&g_O2[(size_t)n * NCLS + cq * 4] = o;
    }
}

// ---------------- edge aggregation, 16 features (4 lanes per edge) ---------
__global__ __launch_bounds__(256)
void k_agg16(const int* __restrict__ src, const int* __restrict__ dst, int E) {
    int t = blockIdx.x * blockDim.x + threadIdx.x;
    int e = t >> 2;
    if (e >= E) return;
    int lane = t & 3;
    int s = src[e];
    int d = dst[e];
    float nr = g_norm[e];
    float4 v = *(const float4*)&g_H2[(size_t)s * NCLS + lane * 4];
    red_add_v4(&g_O2[(size_t)d * NCLS + lane * 4], v.x * nr, v.y * nr, v.z * nr, v.w * nr);
}

// ---------------- final: out = log_softmax(O2 + b2) ------------------------
__global__ __launch_bounds__(256)
void k_lsm(const float* __restrict__ b2, float* __restrict__ out, int Nn) {
    __shared__ float bs[NCLS];
    if (threadIdx.x < NCLS) bs[threadIdx.x] = b2[threadIdx.x];
    __syncthreads();

    int n = blockIdx.x * blockDim.x + threadIdx.x;
    if (n >= Nn) return;

    float v[NCLS];
    #pragma unroll
    for (int cq = 0; cq < 4; cq++) {
        float4 r = *(const float4*)&g_O2[(size_t)n * NCLS + cq * 4];
        v[cq*4+0] = r.x + bs[cq*4+0];
        v[cq*4+1] = r.y + bs[cq*4+1];
        v[cq*4+2] = r.z + bs[cq*4+2];
        v[cq*4+3] = r.w + bs[cq*4+3];
    }
    float m = v[0];
    #pragma unroll
    for (int c = 1; c < NCLS; c++) m = fmaxf(m, v[c]);
    float s = 0.f;
    #pragma unroll
    for (int c = 0; c < NCLS; c++) s += expf(v[c] - m);
    float l = logf(s) + m;
    #pragma unroll
    for (int cq = 0; cq < 4; cq++) {
        float4 o = make_float4(v[cq*4+0]-l, v[cq*4+1]-l, v[cq*4+2]-l, v[cq*4+3]-l);
        *(float4*)&out[(size_t)n * NCLS + cq * 4] = o;
    }
}

// ---------------- launch ----------------------------------------------------
extern "C" void kernel_launch(void* const* d_in, const int* in_sizes, int n_in,
                              void* d_out, int out_size) {
    const float* x   = (const float*)d_in[0];   // [N, 512]
    const int*   ei  = (const int*)  d_in[1];   // [2, E]: src = ei[0:E], dst = ei[E:2E]
    const float* ew  = (const float*)d_in[2];   // [E]
    const float* W1  = (const float*)d_in[3];   // [512, 64]
    const float* b1  = (const float*)d_in[4];   // [64]
    const float* W2  = (const float*)d_in[5];   // [64, 16]
    const float* b2  = (const float*)d_in[6];   // [16]
    float*       out = (float*)d_out;

    const int N = in_sizes[0] / INDIM;
    const int E = in_sizes[2];
    const int* src = ei;
    const int* dst = ei + E;

    const int T = 256;

    // degree / normalization
    k_deg_init<<<(N + T - 1) / T, T>>>(N);
    k_deg_acc <<<(E + T - 1) / T, T>>>(dst, ew, E);
    k_deg_fin <<<(N + T - 1) / T, T>>>(N);
    k_norm    <<<(E + T - 1) / T, T>>>(src, dst, ew, E);

    // layer 1
    k_gemm1 <<<(N + BM - 1) / BM, 256>>>(x, W1, N);
    {
        long long th = (long long)E * 16;
        k_agg64<<<(int)((th + T - 1) / T), T>>>(src, dst, E);
    }

    // layer 2
    k_layer2<<<(N + T - 1) / T, T>>>(b1, W2, N);
    {
        long long th = (long long)E * 4;
        k_agg16<<<(int)((th + T - 1) / T), T>>>(src, dst, E);
    }

    // epilogue
    k_lsm<<<(N + T - 1) / T, T>>>(b2, out, N);
}

// round 5
// speedup vs baseline: 1.0432x; 1.0432x over previous
#include <cuda_runtime.h>
#include <cstdint>

// Problem constants (fixed shapes for this problem instance).
#define NMAX   100000
#define EMAX   1600000
#define INDIM  512
#define HID    64
#define NCLS   16

// ---------------- scratch (device globals; no allocation allowed) ----------
__device__ __align__(256) float g_dis [NMAX];                    // deg -> rsqrt(deg)
__device__ __align__(256) float g_norm[EMAX];                    // per-edge norm
__device__ __align__(256) float g_H  [(size_t)NMAX * HID];       // x @ W1
__device__ __align__(256) float g_O1 [(size_t)NMAX * HID];       // aggregated layer-1
__device__ __align__(256) float g_H2 [(size_t)NMAX * NCLS];      // relu(O1+b1) @ W2
__device__ __align__(256) float g_O2 [(size_t)NMAX * NCLS];      // aggregated layer-2
__device__ __align__(256) float g_Wthi[(size_t)HID * INDIM];     // W1^T hi (tf32)
__device__ __align__(256) float g_Wtlo[(size_t)HID * INDIM];     // W1^T lo residual

__device__ __forceinline__ float to_tf32(float x) {
    float r; asm("cvt.rna.tf32.f32 %0, %1;" : "=f"(r) : "f"(x)); return r;
}

// ---------------- degree / normalization ----------------------------------
__global__ void k_deg_init(int n) {
    int i = blockIdx.x * blockDim.x + threadIdx.x;
    if (i < n) g_dis[i] = 1.0f;
}

__global__ void k_deg_acc(const int* __restrict__ dst, const float* __restrict__ w, int E) {
    int q = blockIdx.x * blockDim.x + threadIdx.x;
    int base = q * 4;
    if (base + 3 < E) {
        int4   d = *(const int4*)&dst[base];
        float4 v = *(const float4*)&w[base];
        atomicAdd(&g_dis[d.x], v.x);
        atomicAdd(&g_dis[d.y], v.y);
        atomicAdd(&g_dis[d.z], v.z);
        atomicAdd(&g_dis[d.w], v.w);
    } else {
        for (int e = base; e < E; e++) atomicAdd(&g_dis[dst[e]], w[e]);
    }
}

__global__ void k_deg_fin(int n) {
    int i = blockIdx.x * blockDim.x + threadIdx.x;
    if (i < n) g_dis[i] = rsqrtf(g_dis[i]);
}

__global__ void k_norm(const int* __restrict__ src, const int* __restrict__ dst,
                       const float* __restrict__ w, int E) {
    int q = blockIdx.x * blockDim.x + threadIdx.x;
    int base = q * 4;
    if (base + 3 < E) {
        int4   s = *(const int4*)&src[base];
        int4   d = *(const int4*)&dst[base];
        float4 v = *(const float4*)&w[base];
        float4 o;
        o.x = g_dis[s.x] * v.x * g_dis[d.x];
        o.y = g_dis[s.y] * v.y * g_dis[d.y];
        o.z = g_dis[s.z] * v.z * g_dis[d.z];
        o.w = g_dis[s.w] * v.w * g_dis[d.w];
        *(float4*)&g_norm[base] = o;
    } else {
        for (int e = base; e < E; e++) g_norm[e] = g_dis[src[e]] * w[e] * g_dis[dst[e]];
    }
}

// ---------------- W1 prep: transpose + tf32 hi/lo split --------------------
__global__ void k_wprep(const float* __restrict__ W1) {
    int i = blockIdx.x * blockDim.x + threadIdx.x;   // i = n*INDIM + k
    if (i < HID * INDIM) {
        int n = i >> 9;
        int k = i & (INDIM - 1);
        float v  = W1[(size_t)k * HID + n];
        float hi = to_tf32(v);
        float lo = to_tf32(v - hi);
        g_Wthi[i] = hi;
        g_Wtlo[i] = lo;
    }
}

// ---------------- GEMM1 via mma.sync tf32 (3-term split) -------------------
// D[128,64] = A[128,512] * B[64,512]^T, fp32 accum.
// 256 threads = 8 warps as 4(m) x 2(n); warp tile 32x32 = 2x4 mma tiles of 16x8.
// Smem pad = 20 words/row: per-lane fragment pattern (l>>2)*20 + (l&3) is
// bank-conflict-free (20*r mod 32 hits distinct multiples of 4 for r<8).
#define GM  128
#define BKK 16

__device__ __forceinline__ void mma_tf32(float* c, const uint32_t* a, const uint32_t* b) {
    asm volatile(
        "mma.sync.aligned.m16n8k8.row.col.f32.tf32.tf32.f32 "
        "{%0,%1,%2,%3}, {%4,%5,%6,%7}, {%8,%9}, {%0,%1,%2,%3};"
        : "+f"(c[0]), "+f"(c[1]), "+f"(c[2]), "+f"(c[3])
        : "r"(a[0]), "r"(a[1]), "r"(a[2]), "r"(a[3]), "r"(b[0]), "r"(b[1]));
}

__global__ __launch_bounds__(256)
void k_gemm1_mma(const float* __restrict__ X, int Nrows) {
    __shared__ uint32_t Ah[GM][20], Al[GM][20];
    __shared__ uint32_t Bh[HID][20], Bl[HID][20];

    const int tid  = threadIdx.x;
    const int lane = tid & 31;
    const int wid  = tid >> 5;
    const int wm   = wid >> 1;          // 0..3
    const int wn   = wid & 1;           // 0..1
    const int gid  = lane >> 2;         // groupID
    const int tig  = lane & 3;          // threadID in group
    const int rowBase = blockIdx.x * GM;

    float C[2][4][4];
    #pragma unroll
    for (int mt = 0; mt < 2; mt++)
        #pragma unroll
        for (int nt = 0; nt < 4; nt++)
            #pragma unroll
            for (int q = 0; q < 4; q++) C[mt][nt][q] = 0.0f;

    for (int c = 0; c < INDIM / BKK; c++) {
        const int k0 = c * BKK;
        // ---- stage A: X tile 128 x 16 (512 float4, 2 per thread) ----
        #pragma unroll
        for (int p = 0; p < 2; p++) {
            int f4 = tid + p * 256;
            int r  = f4 >> 2;
            int kq = f4 & 3;
            int grow = rowBase + r;
            float4 v = make_float4(0.f, 0.f, 0.f, 0.f);
            if (grow < Nrows)
                v = *(const float4*)&X[(size_t)grow * INDIM + k0 + kq * 4];
            float4 h, l;
            h.x = to_tf32(v.x); l.x = to_tf32(v.x - h.x);
            h.y = to_tf32(v.y); l.y = to_tf32(v.y - h.y);
            h.z = to_tf32(v.z); l.z = to_tf32(v.z - h.z);
            h.w = to_tf32(v.w); l.w = to_tf32(v.w - h.w);
            *(float4*)&Ah[r][kq * 4] = h;
            *(float4*)&Al[r][kq * 4] = l;
        }
        // ---- stage B: W^T tile 64 x 16 (256 float4, 1 per thread) ----
        {
            int r  = tid >> 2;          // 0..63
            int kq = tid & 3;
            size_t gi = (size_t)r * INDIM + k0 + kq * 4;
            *(uint4*)&Bh[r][kq * 4] = *(const uint4*)&g_Wthi[gi];
            *(uint4*)&Bl[r][kq * 4] = *(const uint4*)&g_Wtlo[gi];
        }
        __syncthreads();

        #pragma unroll
        for (int ks = 0; ks < BKK / 8; ks++) {
            const int ak = ks * 8 + tig;
            uint32_t ah[2][4], al[2][4];
            #pragma unroll
            for (int mt = 0; mt < 2; mt++) {
                int rb = wm * 32 + mt * 16 + gid;
                ah[mt][0] = Ah[rb][ak];     ah[mt][1] = Ah[rb + 8][ak];
                ah[mt][2] = Ah[rb][ak + 4]; ah[mt][3] = Ah[rb + 8][ak + 4];
                al[mt][0] = Al[rb][ak];     al[mt][1] = Al[rb + 8][ak];
                al[mt][2] = Al[rb][ak + 4]; al[mt][3] = Al[rb + 8][ak + 4];
            }
            uint32_t bh[4][2], bl[4][2];
            #pragma unroll
            for (int nt = 0; nt < 4; nt++) {
                int cb = wn * 32 + nt * 8 + gid;
                bh[nt][0] = Bh[cb][ak]; bh[nt][1] = Bh[cb][ak + 4];
                bl[nt][0] = Bl[cb][ak]; bl[nt][1] = Bl[cb][ak + 4];
            }
            #pragma unroll
            for (int mt = 0; mt < 2; mt++)
                #pragma unroll
                for (int nt = 0; nt < 4; nt++) {
                    mma_tf32(C[mt][nt], ah[mt], bh[nt]);
                    mma_tf32(C[mt][nt], ah[mt], bl[nt]);
                    mma_tf32(C[mt][nt], al[mt], bh[nt]);
                }
        }
        __syncthreads();
    }

    // ---- epilogue: H and O1 = H * dis^2 (self-loop init) ----
    #pragma unroll
    for (int mt = 0; mt < 2; mt++) {
        int r0 = rowBase + wm * 32 + mt * 16 + gid;
        int r1 = r0 + 8;
        if (r0 < Nrows) {
            float d = g_dis[r0]; float sn = d * d;
            float* hrow = &g_H [(size_t)r0 * HID];
            float* orow = &g_O1[(size_t)r0 * HID];
            #pragma unroll
            for (int nt = 0; nt < 4; nt++) {
                int col = wn * 32 + nt * 8 + tig * 2;
                float2 v = make_float2(C[mt][nt][0], C[mt][nt][1]);
                *(float2*)&hrow[col] = v;
                *(float2*)&orow[col] = make_float2(v.x * sn, v.y * sn);
            }
        }
        if (r1 < Nrows) {
            float d = g_dis[r1]; float sn = d * d;
            float* hrow = &g_H [(size_t)r1 * HID];
            float* orow = &g_O1[(size_t)r1 * HID];
            #pragma unroll
            for (int nt = 0; nt < 4; nt++) {
                int col = wn * 32 + nt * 8 + tig * 2;
                float2 v = make_float2(C[mt][nt][2], C[mt][nt][3]);
                *(float2*)&hrow[col] = v;
                *(float2*)&orow[col] = make_float2(v.x * sn, v.y * sn);
            }
        }
    }
}

// ---------------- edge aggregation, 64 features (half-warp per edge) -------
__device__ __forceinline__ void red_add_v4(float* addr, float a, float b, float c, float d) {
    asm volatile("red.global.add.v4.f32 [%0], {%1, %2, %3, %4};"
                 :: "l"(addr), "f"(a), "f"(b), "f"(c), "f"(d) : "memory");
}

__global__ __launch_bounds__(256)
void k_agg64(const int* __restrict__ src, const int* __restrict__ dst, int E) {
    int t = blockIdx.x * blockDim.x + threadIdx.x;
    int e = t >> 4;
    if (e >= E) return;
    int lane = t & 15;
    int s = src[e];
    int d = dst[e];
    float nr = g_norm[e];
    float4 v = *(const float4*)&g_H[(size_t)s * HID + lane * 4];
    red_add_v4(&g_O1[(size_t)d * HID + lane * 4], v.x * nr, v.y * nr, v.z * nr, v.w * nr);
}

// ---------------- layer 2: H2 = relu(O1+b1) @ W2 ; O2 = H2 * selfnorm ------
__global__ __launch_bounds__(256)
void k_layer2(const float* __restrict__ b1, const float* __restrict__ W2, int Nn) {
    __shared__ float Ws[HID * NCLS];
    __shared__ float bs[HID];
    for (int i = threadIdx.x; i < HID * NCLS; i += blockDim.x) Ws[i] = W2[i];
    if (threadIdx.x < HID) bs[threadIdx.x] = b1[threadIdx.x];
    __syncthreads();

    int n = blockIdx.x * blockDim.x + threadIdx.x;
    if (n >= Nn) return;

    float acc[NCLS];
    #pragma unroll
    for (int c = 0; c < NCLS; c++) acc[c] = 0.0f;

    const float* row = &g_O1[(size_t)n * HID];
    #pragma unroll
    for (int jq = 0; jq < HID / 4; jq++) {
        float4 r = *(const float4*)&row[jq * 4];
        float tv[4];
        tv[0] = fmaxf(r.x + bs[jq * 4 + 0], 0.f);
        tv[1] = fmaxf(r.y + bs[jq * 4 + 1], 0.f);
        tv[2] = fmaxf(r.z + bs[jq * 4 + 2], 0.f);
        tv[3] = fmaxf(r.w + bs[jq * 4 + 3], 0.f);
        #pragma unroll
        for (int u = 0; u < 4; u++) {
            int j = jq * 4 + u;
            float tvu = tv[u];
            #pragma unroll
            for (int cq = 0; cq < 4; cq++) {
                float4 w = *(const float4*)&Ws[j * NCLS + cq * 4];
                acc[cq * 4 + 0] += tvu * w.x;
                acc[cq * 4 + 1] += tvu * w.y;
                acc[cq * 4 + 2] += tvu * w.z;
                acc[cq * 4 + 3] += tvu * w.w;
            }
        }
    }

    float d  = g_dis[n];
    float sn = d * d;
    #pragma unroll
    for (int cq = 0; cq < 4; cq++) {
        float4 v = make_float4(acc[cq*4+0], acc[cq*4+1], acc[cq*4+2], acc[cq*4+3]);
        *(float4*)&g_H2[(size_t)n * NCLS + cq * 4] = v;
        float4 o = make_float4(v.x * sn, v.y * sn, v.z * sn, v.w * sn);
        *(float4*)&g_O2[(size_t)n * NCLS + cq * 4] = o;
    }
}

// ---------------- edge aggregation, 16 features (4 lanes per edge) ---------
__global__ __launch_bounds__(256)
void k_agg16(const int* __restrict__ src, const int* __restrict__ dst, int E) {
    int t = blockIdx.x * blockDim.x + threadIdx.x;
    int e = t >> 2;
    if (e >= E) return;
    int lane = t & 3;
    int s = src[e];
    int d = dst[e];
    float nr = g_norm[e];
    float4 v = *(const float4*)&g_H2[(size_t)s * NCLS + lane * 4];
    red_add_v4(&g_O2[(size_t)d * NCLS + lane * 4], v.x * nr, v.y * nr, v.z * nr, v.w * nr);
}

// ---------------- final: out = log_softmax(O2 + b2) ------------------------
__global__ __launch_bounds__(256)
void k_lsm(const float* __restrict__ b2, float* __restrict__ out, int Nn) {
    __shared__ float bs[NCLS];
    if (threadIdx.x < NCLS) bs[threadIdx.x] = b2[threadIdx.x];
    __syncthreads();

    int n = blockIdx.x * blockDim.x + threadIdx.x;
    if (n >= Nn) return;

    float v[NCLS];
    #pragma unroll
    for (int cq = 0; cq < 4; cq++) {
        float4 r = *(const float4*)&g_O2[(size_t)n * NCLS + cq * 4];
        v[cq*4+0] = r.x + bs[cq*4+0];
        v[cq*4+1] = r.y + bs[cq*4+1];
        v[cq*4+2] = r.z + bs[cq*4+2];
        v[cq*4+3] = r.w + bs[cq*4+3];
    }
    float m = v[0];
    #pragma unroll
    for (int c = 1; c < NCLS; c++) m = fmaxf(m, v[c]);
    float s = 0.f;
    #pragma unroll
    for (int c = 0; c < NCLS; c++) s += expf(v[c] - m);
    float l = logf(s) + m;
    #pragma unroll
    for (int cq = 0; cq < 4; cq++) {
        float4 o = make_float4(v[cq*4+0]-l, v[cq*4+1]-l, v[cq*4+2]-l, v[cq*4+3]-l);
        *(float4*)&out[(size_t)n * NCLS + cq * 4] = o;
    }
}

// ---------------- launch ----------------------------------------------------
extern "C" void kernel_launch(void* const* d_in, const int* in_sizes, int n_in,
                              void* d_out, int out_size) {
    const float* x   = (const float*)d_in[0];   // [N, 512]
    const int*   ei  = (const int*)  d_in[1];   // [2, E]
    const float* ew  = (const float*)d_in[2];   // [E]
    const float* W1  = (const float*)d_in[3];   // [512, 64]
    const float* b1  = (const float*)d_in[4];   // [64]
    const float* W2  = (const float*)d_in[5];   // [64, 16]
    const float* b2  = (const float*)d_in[6];   // [16]
    float*       out = (float*)d_out;

    const int N = in_sizes[0] / INDIM;
    const int E = in_sizes[2];
    const int* src = ei;
    const int* dst = ei + E;

    const int T = 256;

    // degree / normalization
    k_deg_init<<<(N + T - 1) / T, T>>>(N);
    {
        int q = (E + 3) / 4;
        k_deg_acc<<<(q + T - 1) / T, T>>>(dst, ew, E);
    }
    k_deg_fin<<<(N + T - 1) / T, T>>>(N);
    {
        int q = (E + 3) / 4;
        k_norm<<<(q + T - 1) / T, T>>>(src, dst, ew, E);
    }

    // W1 prep + layer 1 GEMM (tensor pipe, 3x tf32 split)
    k_wprep<<<(HID * INDIM + T - 1) / T, T>>>(W1);
    k_gemm1_mma<<<(N + GM - 1) / GM, 256>>>(x, N);
    {
        long long th = (long long)E * 16;
        k_agg64<<<(int)((th + T - 1) / T), T>>>(src, dst, E);
    }

    // layer 2
    k_layer2<<<(N + T - 1) / T, T>>>(b1, W2, N);
    {
        long long th = (long long)E * 4;
        k_agg16<<<(int)((th + T - 1) / T), T>>>(src, dst, E);
    }

    // epilogue
    k_lsm<<<(N + T - 1) / T, T>>>(b2, out, N);
}

// round 6
// speedup vs baseline: 1.1021x; 1.0565x over previous
#include <cuda_runtime.h>
#include <cstdint>

// Problem constants (fixed shapes for this problem instance).
#define NMAX   100000
#define EMAX   1600000
#define INDIM  512
#define HID    64
#define NCLS   16

// ---------------- scratch (device globals; no allocation allowed) ----------
__device__ __align__(256) float g_dis [NMAX];                    // deg -> rsqrt(deg)
__device__ __align__(256) float g_norm[EMAX];                    // per-edge norm
__device__ __align__(256) float g_H  [(size_t)NMAX * HID];       // x @ W1
__device__ __align__(256) float g_O1 [(size_t)NMAX * HID];       // aggregated layer-1
__device__ __align__(256) float g_H2 [(size_t)NMAX * NCLS];      // relu(O1+b1) @ W2
__device__ __align__(256) float g_O2 [(size_t)NMAX * NCLS];      // aggregated layer-2
__device__ __align__(256) float g_Wthi[(size_t)HID * INDIM];     // W1^T hi (tf32)
__device__ __align__(256) float g_Wtlo[(size_t)HID * INDIM];     // W1^T lo residual

__device__ __forceinline__ float to_tf32(float x) {
    float r; asm("cvt.rna.tf32.f32 %0, %1;" : "=f"(r) : "f"(x)); return r;
}

// ---------------- prep: deg init (self-loop) + W1 transpose/split ----------
__global__ void k_prep(const float* __restrict__ W1, int n) {
    int i = blockIdx.x * blockDim.x + threadIdx.x;
    if (i < n) g_dis[i] = 1.0f;                       // self-loop weight
    if (i < HID * INDIM) {                            // W1^T tf32 hi/lo split
        int c = i >> 9;
        int k = i & (INDIM - 1);
        float v  = W1[(size_t)k * HID + c];
        float hi = to_tf32(v);
        float lo = to_tf32(v - hi);
        g_Wthi[i] = hi;
        g_Wtlo[i] = lo;
    }
}

__global__ void k_deg_acc(const int* __restrict__ dst, const float* __restrict__ w, int E) {
    int q = blockIdx.x * blockDim.x + threadIdx.x;
    int base = q * 4;
    if (base + 3 < E) {
        int4   d = *(const int4*)&dst[base];
        float4 v = *(const float4*)&w[base];
        atomicAdd(&g_dis[d.x], v.x);
        atomicAdd(&g_dis[d.y], v.y);
        atomicAdd(&g_dis[d.z], v.z);
        atomicAdd(&g_dis[d.w], v.w);
    } else {
        for (int e = base; e < E; e++) atomicAdd(&g_dis[dst[e]], w[e]);
    }
}

__global__ void k_deg_fin(int n) {
    int i = blockIdx.x * blockDim.x + threadIdx.x;
    if (i < n) g_dis[i] = rsqrtf(g_dis[i]);
}

// 8 edges per thread: 16 independent L2 gathers in flight (latency-bound kernel)
__global__ void k_norm(const int* __restrict__ src, const int* __restrict__ dst,
                       const float* __restrict__ w, int E) {
    int q = blockIdx.x * blockDim.x + threadIdx.x;
    int base = q * 8;
    if (base + 7 < E) {
        int4   s0 = *(const int4*)&src[base];
        int4   s1 = *(const int4*)&src[base + 4];
        int4   d0 = *(const int4*)&dst[base];
        int4   d1 = *(const int4*)&dst[base + 4];
        float4 v0 = *(const float4*)&w[base];
        float4 v1 = *(const float4*)&w[base + 4];
        float a0 = g_dis[s0.x], a1 = g_dis[s0.y], a2 = g_dis[s0.z], a3 = g_dis[s0.w];
        float a4 = g_dis[s1.x], a5 = g_dis[s1.y], a6 = g_dis[s1.z], a7 = g_dis[s1.w];
        float b0 = g_dis[d0.x], b1 = g_dis[d0.y], b2 = g_dis[d0.z], b3 = g_dis[d0.w];
        float b4 = g_dis[d1.x], b5 = g_dis[d1.y], b6 = g_dis[d1.z], b7 = g_dis[d1.w];
        float4 o0 = make_float4(a0 * v0.x * b0, a1 * v0.y * b1, a2 * v0.z * b2, a3 * v0.w * b3);
        float4 o1 = make_float4(a4 * v1.x * b4, a5 * v1.y * b5, a6 * v1.z * b6, a7 * v1.w * b7);
        *(float4*)&g_norm[base]     = o0;
        *(float4*)&g_norm[base + 4] = o1;
    } else {
        for (int e = base; e < E; e++) g_norm[e] = g_dis[src[e]] * w[e] * g_dis[dst[e]];
    }
}

// ---------------- GEMM1 via mma.sync tf32 (3-term split) -------------------
// D[128,64] = A[128,512] * B[64,512]^T, fp32 accum.
// 256 threads = 8 warps as 4(m) x 2(n); warp tile 32x32 = 2x4 mma tiles of 16x8.
// Smem pad = 20 words/row: per-lane fragment pattern (l>>2)*20 + (l&3) is
// bank-conflict-free (20*r mod 32 hits distinct multiples of 4 for r<8).
#define GM  128
#define BKK 16

__device__ __forceinline__ void mma_tf32(float* c, const uint32_t* a, const uint32_t* b) {
    asm volatile(
        "mma.sync.aligned.m16n8k8.row.col.f32.tf32.tf32.f32 "
        "{%0,%1,%2,%3}, {%4,%5,%6,%7}, {%8,%9}, {%0,%1,%2,%3};"
        : "+f"(c[0]), "+f"(c[1]), "+f"(c[2]), "+f"(c[3])
        : "r"(a[0]), "r"(a[1]), "r"(a[2]), "r"(a[3]), "r"(b[0]), "r"(b[1]));
}

__global__ __launch_bounds__(256)
void k_gemm1_mma(const float* __restrict__ X, int Nrows) {
    __shared__ uint32_t Ah[GM][20], Al[GM][20];
    __shared__ uint32_t Bh[HID][20], Bl[HID][20];

    const int tid  = threadIdx.x;
    const int lane = tid & 31;
    const int wid  = tid >> 5;
    const int wm   = wid >> 1;          // 0..3
    const int wn   = wid & 1;           // 0..1
    const int gid  = lane >> 2;         // groupID
    const int tig  = lane & 3;          // threadID in group
    const int rowBase = blockIdx.x * GM;

    float C[2][4][4];
    #pragma unroll
    for (int mt = 0; mt < 2; mt++)
        #pragma unroll
        for (int nt = 0; nt < 4; nt++)
            #pragma unroll
            for (int q = 0; q < 4; q++) C[mt][nt][q] = 0.0f;

    for (int c = 0; c < INDIM / BKK; c++) {
        const int k0 = c * BKK;
        // ---- stage A: X tile 128 x 16 (512 float4, 2 per thread) ----
        #pragma unroll
        for (int p = 0; p < 2; p++) {
            int f4 = tid + p * 256;
            int r  = f4 >> 2;
            int kq = f4 & 3;
            int grow = rowBase + r;
            float4 v = make_float4(0.f, 0.f, 0.f, 0.f);
            if (grow < Nrows)
                v = *(const float4*)&X[(size_t)grow * INDIM + k0 + kq * 4];
            float4 h, l;
            h.x = to_tf32(v.x); l.x = to_tf32(v.x - h.x);
            h.y = to_tf32(v.y); l.y = to_tf32(v.y - h.y);
            h.z = to_tf32(v.z); l.z = to_tf32(v.z - h.z);
            h.w = to_tf32(v.w); l.w = to_tf32(v.w - h.w);
            *(float4*)&Ah[r][kq * 4] = h;
            *(float4*)&Al[r][kq * 4] = l;
        }
        // ---- stage B: W^T tile 64 x 16 (256 float4, 1 per thread) ----
        {
            int r  = tid >> 2;          // 0..63
            int kq = tid & 3;
            size_t gi = (size_t)r * INDIM + k0 + kq * 4;
            *(uint4*)&Bh[r][kq * 4] = *(const uint4*)&g_Wthi[gi];
            *(uint4*)&Bl[r][kq * 4] = *(const uint4*)&g_Wtlo[gi];
        }
        __syncthreads();

        #pragma unroll
        for (int ks = 0; ks < BKK / 8; ks++) {
            const int ak = ks * 8 + tig;
            uint32_t ah[2][4], al[2][4];
            #pragma unroll
            for (int mt = 0; mt < 2; mt++) {
                int rb = wm * 32 + mt * 16 + gid;
                ah[mt][0] = Ah[rb][ak];     ah[mt][1] = Ah[rb + 8][ak];
                ah[mt][2] = Ah[rb][ak + 4]; ah[mt][3] = Ah[rb + 8][ak + 4];
                al[mt][0] = Al[rb][ak];     al[mt][1] = Al[rb + 8][ak];
                al[mt][2] = Al[rb][ak + 4]; al[mt][3] = Al[rb + 8][ak + 4];
            }
            uint32_t bh[4][2], bl[4][2];
            #pragma unroll
            for (int nt = 0; nt < 4; nt++) {
                int cb = wn * 32 + nt * 8 + gid;
                bh[nt][0] = Bh[cb][ak]; bh[nt][1] = Bh[cb][ak + 4];
                bl[nt][0] = Bl[cb][ak]; bl[nt][1] = Bl[cb][ak + 4];
            }
            #pragma unroll
            for (int mt = 0; mt < 2; mt++)
                #pragma unroll
                for (int nt = 0; nt < 4; nt++) {
                    mma_tf32(C[mt][nt], ah[mt], bh[nt]);
                    mma_tf32(C[mt][nt], ah[mt], bl[nt]);
                    mma_tf32(C[mt][nt], al[mt], bh[nt]);
                }
        }
        __syncthreads();
    }

    // ---- epilogue: H and O1 = H * dis^2 (self-loop init) ----
    #pragma unroll
    for (int mt = 0; mt < 2; mt++) {
        int r0 = rowBase + wm * 32 + mt * 16 + gid;
        int r1 = r0 + 8;
        if (r0 < Nrows) {
            float d = g_dis[r0]; float sn = d * d;
            float* hrow = &g_H [(size_t)r0 * HID];
            float* orow = &g_O1[(size_t)r0 * HID];
            #pragma unroll
            for (int nt = 0; nt < 4; nt++) {
                int col = wn * 32 + nt * 8 + tig * 2;
                float2 v = make_float2(C[mt][nt][0], C[mt][nt][1]);
                *(float2*)&hrow[col] = v;
                *(float2*)&orow[col] = make_float2(v.x * sn, v.y * sn);
            }
        }
        if (r1 < Nrows) {
            float d = g_dis[r1]; float sn = d * d;
            float* hrow = &g_H [(size_t)r1 * HID];
            float* orow = &g_O1[(size_t)r1 * HID];
            #pragma unroll
            for (int nt = 0; nt < 4; nt++) {
                int col = wn * 32 + nt * 8 + tig * 2;
                float2 v = make_float2(C[mt][nt][2], C[mt][nt][3]);
                *(float2*)&hrow[col] = v;
                *(float2*)&orow[col] = make_float2(v.x * sn, v.y * sn);
            }
        }
    }
}

// ---------------- edge aggregation, 64 features (half-warp per edge) -------
__device__ __forceinline__ void red_add_v4(float* addr, float a, float b, float c, float d) {
    asm volatile("red.global.add.v4.f32 [%0], {%1, %2, %3, %4};"
                 :: "l"(addr), "f"(a), "f"(b), "f"(c), "f"(d) : "memory");
}

__global__ __launch_bounds__(256)
void k_agg64(const int* __restrict__ src, const int* __restrict__ dst, int E) {
    int t = blockIdx.x * blockDim.x + threadIdx.x;
    int e = t >> 4;
    if (e >= E) return;
    int lane = t & 15;
    int s = src[e];
    int d = dst[e];
    float nr = g_norm[e];
    float4 v = *(const float4*)&g_H[(size_t)s * HID + lane * 4];
    red_add_v4(&g_O1[(size_t)d * HID + lane * 4], v.x * nr, v.y * nr, v.z * nr, v.w * nr);
}

// ---------------- layer 2: H2 = relu(O1+b1) @ W2 ; O2 = H2 * selfnorm ------
__global__ __launch_bounds__(256)
void k_layer2(const float* __restrict__ b1, const float* __restrict__ W2, int Nn) {
    __shared__ float Ws[HID * NCLS];
    __shared__ float bs[HID];
    for (int i = threadIdx.x; i < HID * NCLS; i += blockDim.x) Ws[i] = W2[i];
    if (threadIdx.x < HID) bs[threadIdx.x] = b1[threadIdx.x];
    __syncthreads();

    int n = blockIdx.x * blockDim.x + threadIdx.x;
    if (n >= Nn) return;

    float acc[NCLS];
    #pragma unroll
    for (int c = 0; c < NCLS; c++) acc[c] = 0.0f;

    const float* row = &g_O1[(size_t)n * HID];
    #pragma unroll
    for (int jq = 0; jq < HID / 4; jq++) {
        float4 r = *(const float4*)&row[jq * 4];
        float tv[4];
        tv[0] = fmaxf(r.x + bs[jq * 4 + 0], 0.f);
        tv[1] = fmaxf(r.y + bs[jq * 4 + 1], 0.f);
        tv[2] = fmaxf(r.z + bs[jq * 4 + 2], 0.f);
        tv[3] = fmaxf(r.w + bs[jq * 4 + 3], 0.f);
        #pragma unroll
        for (int u = 0; u < 4; u++) {
            int j = jq * 4 + u;
            float tvu = tv[u];
            #pragma unroll
            for (int cq = 0; cq < 4; cq++) {
                float4 w = *(const float4*)&Ws[j * NCLS + cq * 4];
                acc[cq * 4 + 0] += tvu * w.x;
                acc[cq * 4 + 1] += tvu * w.y;
                acc[cq * 4 + 2] += tvu * w.z;
                acc[cq * 4 + 3] += tvu * w.w;
            }
        }
    }

    float d  = g_dis[n];
    float sn = d * d;
    #pragma unroll
    for (int cq = 0; cq < 4; cq++) {
        float4 v = make_float4(acc[cq*4+0], acc[cq*4+1], acc[cq*4+2], acc[cq*4+3]);
        *(float4*)&g_H2[(size_t)n * NCLS + cq * 4] = v;
        float4 o = make_float4(v.x * sn, v.y * sn, v.z * sn, v.w * sn);
        *(float4*)&g_O2[(size_t)n * NCLS + cq * 4] = o;
    }
}

// ---------------- edge aggregation, 16 features (4 lanes per edge) ---------
__global__ __launch_bounds__(256)
void k_agg16(const int* __restrict__ src, const int* __restrict__ dst, int E) {
    int t = blockIdx.x * blockDim.x + threadIdx.x;
    int e = t >> 2;
    if (e >= E) return;
    int lane = t & 3;
    int s = src[e];
    int d = dst[e];
    float nr = g_norm[e];
    float4 v = *(const float4*)&g_H2[(size_t)s * NCLS + lane * 4];
    red_add_v4(&g_O2[(size_t)d * NCLS + lane * 4], v.x * nr, v.y * nr, v.z * nr, v.w * nr);
}

// ---------------- final: out = log_softmax(O2 + b2) ------------------------
__global__ __launch_bounds__(256)
void k_lsm(const float* __restrict__ b2, float* __restrict__ out, int Nn) {
    __shared__ float bs[NCLS];
    if (threadIdx.x < NCLS) bs[threadIdx.x] = b2[threadIdx.x];
    __syncthreads();

    int n = blockIdx.x * blockDim.x + threadIdx.x;
    if (n >= Nn) return;

    float v[NCLS];
    #pragma unroll
    for (int cq = 0; cq < 4; cq++) {
        float4 r = *(const float4*)&g_O2[(size_t)n * NCLS + cq * 4];
        v[cq*4+0] = r.x + bs[cq*4+0];
        v[cq*4+1] = r.y + bs[cq*4+1];
        v[cq*4+2] = r.z + bs[cq*4+2];
        v[cq*4+3] = r.w + bs[cq*4+3];
    }
    float m = v[0];
    #pragma unroll
    for (int c = 1; c < NCLS; c++) m = fmaxf(m, v[c]);
    float s = 0.f;
    #pragma unroll
    for (int c = 0; c < NCLS; c++) s += expf(v[c] - m);
    float l = logf(s) + m;
    #pragma unroll
    for (int cq = 0; cq < 4; cq++) {
        float4 o = make_float4(v[cq*4+0]-l, v[cq*4+1]-l, v[cq*4+2]-l, v[cq*4+3]-l);
        *(float4*)&out[(size_t)n * NCLS + cq * 4] = o;
    }
}

// ---------------- launch ----------------------------------------------------
extern "C" void kernel_launch(void* const* d_in, const int* in_sizes, int n_in,
                              void* d_out, int out_size) {
    const float* x   = (const float*)d_in[0];   // [N, 512]
    const int*   ei  = (const int*)  d_in[1];   // [2, E]
    const float* ew  = (const float*)d_in[2];   // [E]
    const float* W1  = (const float*)d_in[3];   // [512, 64]
    const float* b1  = (const float*)d_in[4];   // [64]
    const float* W2  = (const float*)d_in[5];   // [64, 16]
    const float* b2  = (const float*)d_in[6];   // [16]
    float*       out = (float*)d_out;

    const int N = in_sizes[0] / INDIM;
    const int E = in_sizes[2];
    const int* src = ei;
    const int* dst = ei + E;

    const int T = 256;

    // 1: deg self-loop init + W1 transpose/tf32 split (fused, independent ranges)
    k_prep<<<(N + T - 1) / T, T>>>(W1, N);
    // 2: weighted in-degree
    {
        int q = (E + 3) / 4;
        k_deg_acc<<<(q + T - 1) / T, T>>>(dst, ew, E);
    }
    // 3: deg -> rsqrt(deg)
    k_deg_fin<<<(N + T - 1) / T, T>>>(N);
    // 4: layer-1 GEMM (tensor pipe, 3x tf32 split) — profiled slot
    k_gemm1_mma<<<(N + GM - 1) / GM, 256>>>(x, N);
    // 5: per-edge norm (independent of GEMM; needed only before agg64)
    {
        int q = (E + 7) / 8;
        k_norm<<<(q + T - 1) / T, T>>>(src, dst, ew, E);
    }
    // 6: layer-1 aggregation
    {
        long long th = (long long)E * 16;
        k_agg64<<<(int)((th + T - 1) / T), T>>>(src, dst, E);
    }
    // 7: layer 2 dense
    k_layer2<<<(N + T - 1) / T, T>>>(b1, W2, N);
    // 8: layer-2 aggregation
    {
        long long th = (long long)E * 4;
        k_agg16<<<(int)((th + T - 1) / T), T>>>(src, dst, E);
    }
    // 9: log-softmax epilogue
    k_lsm<<<(N + T - 1) / T, T>>>(b2, out, N);
}

// round 10
// speedup vs baseline: 1.2304x; 1.1163x over previous
#include <cuda_runtime.h>
#include <cstdint>

// Problem constants (fixed shapes for this problem instance).
#define NMAX   100000
#define EMAX   1600000
#define INDIM  512
#define HID    64
#define NCLS   16

// ---------------- scratch (device globals; no allocation allowed) ----------
__device__ __align__(256) float g_dis [NMAX];                    // deg -> rsqrt(deg)
__device__ __align__(256) float g_norm[EMAX];                    // per-edge norm
__device__ __align__(256) float g_H  [(size_t)NMAX * HID];       // x @ W1
__device__ __align__(256) float g_O1 [(size_t)NMAX * HID];       // aggregated layer-1
__device__ __align__(256) float g_H2 [(size_t)NMAX * NCLS];      // relu(O1+b1) @ W2
__device__ __align__(256) float g_O2 [(size_t)NMAX * NCLS];      // aggregated layer-2
__device__ __align__(256) float g_Wthi[(size_t)HID * INDIM];     // W1^T hi (tf32)
__device__ __align__(256) float g_Wtlo[(size_t)HID * INDIM];     // W1^T lo residual

__device__ __forceinline__ float to_tf32(float x) {
    float r; asm("cvt.rna.tf32.f32 %0, %1;" : "=f"(r) : "f"(x)); return r;
}

// ---------------- prep: deg init (self-loop) + W1 transpose/split ----------
__global__ void k_prep(const float* __restrict__ W1, int n) {
    int i = blockIdx.x * blockDim.x + threadIdx.x;
    if (i < n) g_dis[i] = 1.0f;                       // self-loop weight
    if (i < HID * INDIM) {                            // W1^T tf32 hi/lo split
        int c = i >> 9;
        int k = i & (INDIM - 1);
        float v  = W1[(size_t)k * HID + c];
        float hi = to_tf32(v);
        float lo = to_tf32(v - hi);
        g_Wthi[i] = hi;
        g_Wtlo[i] = lo;
    }
}

__global__ void k_deg_acc(const int* __restrict__ dst, const float* __restrict__ w, int E) {
    int q = blockIdx.x * blockDim.x + threadIdx.x;
    int base = q * 4;
    if (base + 3 < E) {
        int4   d = *(const int4*)&dst[base];
        float4 v = *(const float4*)&w[base];
        atomicAdd(&g_dis[d.x], v.x);
        atomicAdd(&g_dis[d.y], v.y);
        atomicAdd(&g_dis[d.z], v.z);
        atomicAdd(&g_dis[d.w], v.w);
    } else {
        for (int e = base; e < E; e++) atomicAdd(&g_dis[dst[e]], w[e]);
    }
}

__global__ void k_deg_fin(int n) {
    int i = blockIdx.x * blockDim.x + threadIdx.x;
    if (i < n) g_dis[i] = rsqrtf(g_dis[i]);
}

// 8 edges per thread: 16 independent L2 gathers in flight (latency-bound kernel)
__global__ void k_norm(const int* __restrict__ src, const int* __restrict__ dst,
                       const float* __restrict__ w, int E) {
    int q = blockIdx.x * blockDim.x + threadIdx.x;
    int base = q * 8;
    if (base + 7 < E) {
        int4   s0 = *(const int4*)&src[base];
        int4   s1 = *(const int4*)&src[base + 4];
        int4   d0 = *(const int4*)&dst[base];
        int4   d1 = *(const int4*)&dst[base + 4];
        float4 v0 = *(const float4*)&w[base];
        float4 v1 = *(const float4*)&w[base + 4];
        float a0 = g_dis[s0.x], a1 = g_dis[s0.y], a2 = g_dis[s0.z], a3 = g_dis[s0.w];
        float a4 = g_dis[s1.x], a5 = g_dis[s1.y], a6 = g_dis[s1.z], a7 = g_dis[s1.w];
        float b0 = g_dis[d0.x], b1 = g_dis[d0.y], b2 = g_dis[d0.z], b3 = g_dis[d0.w];
        float b4 = g_dis[d1.x], b5 = g_dis[d1.y], b6 = g_dis[d1.z], b7 = g_dis[d1.w];
        float4 o0 = make_float4(a0 * v0.x * b0, a1 * v0.y * b1, a2 * v0.z * b2, a3 * v0.w * b3);
        float4 o1 = make_float4(a4 * v1.x * b4, a5 * v1.y * b5, a6 * v1.z * b6, a7 * v1.w * b7);
        *(float4*)&g_norm[base]     = o0;
        *(float4*)&g_norm[base + 4] = o1;
    } else {
        for (int e = base; e < E; e++) g_norm[e] = g_dis[src[e]] * w[e] * g_dis[dst[e]];
    }
}

// ---------------- GEMM1 via mma.sync tf32 (2-term split) -------------------
// D[128,64] = A[128,512] * B[64,512]^T, fp32 accum.
// Split: A*B ~= Ahi*Bhi + Ahi*Blo (dropped Alo*Bhi term ~1.5e-4 rel, << 1e-3).
// 256 threads = 8 warps as 4(m) x 2(n); warp tile 32x32 = 2x4 mma tiles of 16x8.
// Smem pad = 20 words/row: per-lane fragment pattern (l>>2)*20 + (l&3) is
// bank-conflict-free (20*r mod 32 hits distinct multiples of 4 for r<8).
#define GM  128
#define BKK 16

__device__ __forceinline__ void mma_tf32(float* c, const uint32_t* a, const uint32_t* b) {
    asm volatile(
        "mma.sync.aligned.m16n8k8.row.col.f32.tf32.tf32.f32 "
        "{%0,%1,%2,%3}, {%4,%5,%6,%7}, {%8,%9}, {%0,%1,%2,%3};"
        : "+f"(c[0]), "+f"(c[1]), "+f"(c[2]), "+f"(c[3])
        : "r"(a[0]), "r"(a[1]), "r"(a[2]), "r"(a[3]), "r"(b[0]), "r"(b[1]));
}

__global__ __launch_bounds__(256)
void k_gemm1_mma(const float* __restrict__ X, int Nrows) {
    __shared__ uint32_t Ah[GM][20];
    __shared__ uint32_t Bh[HID][20], Bl[HID][20];

    const int tid  = threadIdx.x;
    const int lane = tid & 31;
    const int wid  = tid >> 5;
    const int wm   = wid >> 1;          // 0..3
    const int wn   = wid & 1;           // 0..1
    const int gid  = lane >> 2;         // groupID
    const int tig  = lane & 3;          // threadID in group
    const int rowBase = blockIdx.x * GM;

    float C[2][4][4];
    #pragma unroll
    for (int mt = 0; mt < 2; mt++)
        #pragma unroll
        for (int nt = 0; nt < 4; nt++)
            #pragma unroll
            for (int q = 0; q < 4; q++) C[mt][nt][q] = 0.0f;

    for (int c = 0; c < INDIM / BKK; c++) {
        const int k0 = c * BKK;
        // ---- stage A: X tile 128 x 16 (512 float4, 2 per thread, hi only) ----
        #pragma unroll
        for (int p = 0; p < 2; p++) {
            int f4 = tid + p * 256;
            int r  = f4 >> 2;
            int kq = f4 & 3;
            int grow = rowBase + r;
            float4 v = make_float4(0.f, 0.f, 0.f, 0.f);
            if (grow < Nrows)
                v = *(const float4*)&X[(size_t)grow * INDIM + k0 + kq * 4];
            float4 h;
            h.x = to_tf32(v.x);
            h.y = to_tf32(v.y);
            h.z = to_tf32(v.z);
            h.w = to_tf32(v.w);
            *(float4*)&Ah[r][kq * 4] = h;
        }
        // ---- stage B: W^T tile 64 x 16 hi+lo (256 float4 each, 1 per thread) ----
        {
            int r  = tid >> 2;          // 0..63
            int kq = tid & 3;
            size_t gi = (size_t)r * INDIM + k0 + kq * 4;
            *(uint4*)&Bh[r][kq * 4] = *(const uint4*)&g_Wthi[gi];
            *(uint4*)&Bl[r][kq * 4] = *(const uint4*)&g_Wtlo[gi];
        }
        __syncthreads();

        #pragma unroll
        for (int ks = 0; ks < BKK / 8; ks++) {
            const int ak = ks * 8 + tig;
            uint32_t ah[2][4];
            #pragma unroll
            for (int mt = 0; mt < 2; mt++) {
                int rb = wm * 32 + mt * 16 + gid;
                ah[mt][0] = Ah[rb][ak];     ah[mt][1] = Ah[rb + 8][ak];
                ah[mt][2] = Ah[rb][ak + 4]; ah[mt][3] = Ah[rb + 8][ak + 4];
            }
            uint32_t bh[4][2], bl[4][2];
            #pragma unroll
            for (int nt = 0; nt < 4; nt++) {
                int cb = wn * 32 + nt * 8 + gid;
                bh[nt][0] = Bh[cb][ak]; bh[nt][1] = Bh[cb][ak + 4];
                bl[nt][0] = Bl[cb][ak]; bl[nt][1] = Bl[cb][ak + 4];
            }
            #pragma unroll
            for (int mt = 0; mt < 2; mt++)
                #pragma unroll
                for (int nt = 0; nt < 4; nt++) {
                    mma_tf32(C[mt][nt], ah[mt], bh[nt]);
                    mma_tf32(C[mt][nt], ah[mt], bl[nt]);
                }
        }
        __syncthreads();
    }

    // ---- epilogue: H and O1 = H * dis^2 (self-loop init) ----
    #pragma unroll
    for (int mt = 0; mt < 2; mt++) {
        int r0 = rowBase + wm * 32 + mt * 16 + gid;
        int r1 = r0 + 8;
        if (r0 < Nrows) {
            float d = g_dis[r0]; float sn = d * d;
            float* hrow = &g_H [(size_t)r0 * HID];
            float* orow = &g_O1[(size_t)r0 * HID];
            #pragma unroll
            for (int nt = 0; nt < 4; nt++) {
                int col = wn * 32 + nt * 8 + tig * 2;
                float2 v = make_float2(C[mt][nt][0], C[mt][nt][1]);
                *(float2*)&hrow[col] = v;
                *(float2*)&orow[col] = make_float2(v.x * sn, v.y * sn);
            }
        }
        if (r1 < Nrows) {
            float d = g_dis[r1]; float sn = d * d;
            float* hrow = &g_H [(size_t)r1 * HID];
            float* orow = &g_O1[(size_t)r1 * HID];
            #pragma unroll
            for (int nt = 0; nt < 4; nt++) {
                int col = wn * 32 + nt * 8 + tig * 2;
                float2 v = make_float2(C[mt][nt][2], C[mt][nt][3]);
                *(float2*)&hrow[col] = v;
                *(float2*)&orow[col] = make_float2(v.x * sn, v.y * sn);
            }
        }
    }
}

// ---------------- edge aggregation, 64 features (half-warp per edge) -------
__device__ __forceinline__ void red_add_v4(float* addr, float a, float b, float c, float d) {
    asm volatile("red.global.add.v4.f32 [%0], {%1, %2, %3, %4};"
                 :: "l"(addr), "f"(a), "f"(b), "f"(c), "f"(d) : "memory");
}

__global__ __launch_bounds__(256)
void k_agg64(const int* __restrict__ src, const int* __restrict__ dst, int E) {
    int t = blockIdx.x * blockDim.x + threadIdx.x;
    int e = t >> 4;
    if (e >= E) return;
    int lane = t & 15;
    int s = src[e];
    int d = dst[e];
    float nr = g_norm[e];
    float4 v = *(const float4*)&g_H[(size_t)s * HID + lane * 4];
    red_add_v4(&g_O1[(size_t)d * HID + lane * 4], v.x * nr, v.y * nr, v.z * nr, v.w * nr);
}

// ---------------- layer 2: H2 = relu(O1+b1) @ W2 ; O2 = H2 * selfnorm ------
__global__ __launch_bounds__(256)
void k_layer2(const float* __restrict__ b1, const float* __restrict__ W2, int Nn) {
    __shared__ float Ws[HID * NCLS];
    __shared__ float bs[HID];
    for (int i = threadIdx.x; i < HID * NCLS; i += blockDim.x) Ws[i] = W2[i];
    if (threadIdx.x < HID) bs[threadIdx.x] = b1[threadIdx.x];
    __syncthreads();

    int n = blockIdx.x * blockDim.x + threadIdx.x;
    if (n >= Nn) return;

    float acc[NCLS];
    #pragma unroll
    for (int c = 0; c < NCLS; c++) acc[c] = 0.0f;

    const float* row = &g_O1[(size_t)n * HID];
    #pragma unroll
    for (int jq = 0; jq < HID / 4; jq++) {
        float4 r = *(const float4*)&row[jq * 4];
        float tv[4];
        tv[0] = fmaxf(r.x + bs[jq * 4 + 0], 0.f);
        tv[1] = fmaxf(r.y + bs[jq * 4 + 1], 0.f);
        tv[2] = fmaxf(r.z + bs[jq * 4 + 2], 0.f);
        tv[3] = fmaxf(r.w + bs[jq * 4 + 3], 0.f);
        #pragma unroll
        for (int u = 0; u < 4; u++) {
            int j = jq * 4 + u;
            float tvu = tv[u];
            #pragma unroll
            for (int cq = 0; cq < 4; cq++) {
                float4 w = *(const float4*)&Ws[j * NCLS + cq * 4];
                acc[cq * 4 + 0] += tvu * w.x;
                acc[cq * 4 + 1] += tvu * w.y;
                acc[cq * 4 + 2] += tvu * w.z;
                acc[cq * 4 + 3] += tvu * w.w;
            }
        }
    }

    float d  = g_dis[n];
    float sn = d * d;
    #pragma unroll
    for (int cq = 0; cq < 4; cq++) {
        float4 v = make_float4(acc[cq*4+0], acc[cq*4+1], acc[cq*4+2], acc[cq*4+3]);
        *(float4*)&g_H2[(size_t)n * NCLS + cq * 4] = v;
        float4 o = make_float4(v.x * sn, v.y * sn, v.z * sn, v.w * sn);
        *(float4*)&g_O2[(size_t)n * NCLS + cq * 4] = o;
    }
}

// ---------------- edge aggregation, 16 features (4 lanes per edge) ---------
__global__ __launch_bounds__(256)
void k_agg16(const int* __restrict__ src, const int* __restrict__ dst, int E) {
    int t = blockIdx.x * blockDim.x + threadIdx.x;
    int e = t >> 2;
    if (e >= E) return;
    int lane = t & 3;
    int s = src[e];
    int d = dst[e];
    float nr = g_norm[e];
    float4 v = *(const float4*)&g_H2[(size_t)s * NCLS + lane * 4];
    red_add_v4(&g_O2[(size_t)d * NCLS + lane * 4], v.x * nr, v.y * nr, v.z * nr, v.w * nr);
}

// ---------------- final: out = log_softmax(O2 + b2) ------------------------
__global__ __launch_bounds__(256)
void k_lsm(const float* __restrict__ b2, float* __restrict__ out, int Nn) {
    __shared__ float bs[NCLS];
    if (threadIdx.x < NCLS) bs[threadIdx.x] = b2[threadIdx.x];
    __syncthreads();

    int n = blockIdx.x * blockDim.x + threadIdx.x;
    if (n >= Nn) return;

    float v[NCLS];
    #pragma unroll
    for (int cq = 0; cq < 4; cq++) {
        float4 r = *(const float4*)&g_O2[(size_t)n * NCLS + cq * 4];
        v[cq*4+0] = r.x + bs[cq*4+0];
        v[cq*4+1] = r.y + bs[cq*4+1];
        v[cq*4+2] = r.z + bs[cq*4+2];
        v[cq*4+3] = r.w + bs[cq*4+3];
    }
    float m = v[0];
    #pragma unroll
    for (int c = 1; c < NCLS; c++) m = fmaxf(m, v[c]);
    float s = 0.f;
    #pragma unroll
    for (int c = 0; c < NCLS; c++) s += expf(v[c] - m);
    float l = logf(s) + m;
    #pragma unroll
    for (int cq = 0; cq < 4; cq++) {
        float4 o = make_float4(v[cq*4+0]-l, v[cq*4+1]-l, v[cq*4+2]-l, v[cq*4+3]-l);
        *(float4*)&out[(size_t)n * NCLS + cq * 4] = o;
    }
}

// ---------------- launch ----------------------------------------------------
extern "C" void kernel_launch(void* const* d_in, const int* in_sizes, int n_in,
                              void* d_out, int out_size) {
    const float* x   = (const float*)d_in[0];   // [N, 512]
    const int*   ei  = (const int*)  d_in[1];   // [2, E]
    const float* ew  = (const float*)d_in[2];   // [E]
    const float* W1  = (const float*)d_in[3];   // [512, 64]
    const float* b1  = (const float*)d_in[4];   // [64]
    const float* W2  = (const float*)d_in[5];   // [64, 16]
    const float* b2  = (const float*)d_in[6];   // [16]
    float*       out = (float*)d_out;

    const int N = in_sizes[0] / INDIM;
    const int E = in_sizes[2];
    const int* src = ei;
    const int* dst = ei + E;

    const int T = 256;

    // 1: deg self-loop init + W1 transpose/tf32 split (fused, independent ranges)
    k_prep<<<(N + T - 1) / T, T>>>(W1, N);
    // 2: weighted in-degree
    {
        int q = (E + 3) / 4;
        k_deg_acc<<<(q + T - 1) / T, T>>>(dst, ew, E);
    }
    // 3: deg -> rsqrt(deg)
    k_deg_fin<<<(N + T - 1) / T, T>>>(N);
    // 4: layer-1 GEMM (tensor pipe, 2x tf32 split) — profiled slot
    k_gemm1_mma<<<(N + GM - 1) / GM, 256>>>(x, N);
    // 5: per-edge norm (independent of GEMM; needed only before agg64)
    {
        int q = (E + 7) / 8;
        k_norm<<<(q + T - 1) / T, T>>>(src, dst, ew, E);
    }
    // 6: layer-1 aggregation
    {
        long long th = (long long)E * 16;
        k_agg64<<<(int)((th + T - 1) / T), T>>>(src, dst, E);
    }
    // 7: layer 2 dense
    k_layer2<<<(N + T - 1) / T, T>>>(b1, W2, N);
    // 8: layer-2 aggregation
    {
        long long th = (long long)E * 4;
        k_agg16<<<(int)((th + T - 1) / T), T>>>(src, dst, E);
    }
    // 9: log-softmax epilogue
    k_lsm<<<(N + T - 1) / T, T>>>(b2, out, N);
}

// round 11
// speedup vs baseline: 1.4717x; 1.1961x over previous
#include <cuda_runtime.h>
#include <cstdint>

// Problem constants (fixed shapes for this problem instance).
#define NMAX   100000
#define EMAX   1600000
#define INDIM  512
#define HID    64
#define NCLS   16

// ---------------- scratch (device globals; no allocation allowed) ----------
__device__ __align__(256) float g_dis [NMAX];                    // deg -> rsqrt(deg)
__device__ __align__(256) float g_norm[EMAX];                    // per-edge norm
__device__ __align__(256) float g_H  [(size_t)NMAX * HID];       // x @ W1
__device__ __align__(256) float g_O1 [(size_t)NMAX * HID];       // aggregated layer-1
__device__ __align__(256) float g_H2 [(size_t)NMAX * NCLS];      // relu(O1+b1) @ W2
__device__ __align__(256) float g_O2 [(size_t)NMAX * NCLS];      // aggregated layer-2
// W1^T as packed bf16x2 over k-pairs: [n=0..63][kpair=0..255]
__device__ __align__(256) uint32_t g_Wbhi[(size_t)HID * INDIM / 2];
__device__ __align__(256) uint32_t g_Wblo[(size_t)HID * INDIM / 2];

// pack two floats as bf16x2: result.lo = bf16(lo), result.hi = bf16(hi)
__device__ __forceinline__ uint32_t bf16x2(float hi, float lo) {
    uint32_t r;
    asm("cvt.rn.bf16x2.f32 %0, %1, %2;" : "=r"(r) : "f"(hi), "f"(lo));
    return r;
}

// ---------------- prep: deg init (self-loop) + W1 bf16 hi/lo split ---------
__global__ void k_prep(const float* __restrict__ W1, int n) {
    int i = blockIdx.x * blockDim.x + threadIdx.x;
    if (i < n) g_dis[i] = 1.0f;                       // self-loop weight
    if (i < HID * INDIM / 2) {                        // W1^T bf16 hi/lo packed
        int c  = i >> 8;                              // output column 0..63
        int kp = i & 255;                             // k-pair 0..255
        float v0 = W1[(size_t)(2 * kp)     * HID + c];
        float v1 = W1[(size_t)(2 * kp + 1) * HID + c];
        uint32_t h = bf16x2(v1, v0);
        // bf16 -> f32 is just a 16-bit left shift of the pattern
        float f0 = __uint_as_float(h << 16);
        float f1 = __uint_as_float(h & 0xFFFF0000u);
        uint32_t l = bf16x2(v1 - f1, v0 - f0);
        g_Wbhi[i] = h;
        g_Wblo[i] = l;
    }
}

__global__ void k_deg_acc(const int* __restrict__ dst, const float* __restrict__ w, int E) {
    int q = blockIdx.x * blockDim.x + threadIdx.x;
    int base = q * 4;
    if (base + 3 < E) {
        int4   d = *(const int4*)&dst[base];
        float4 v = *(const float4*)&w[base];
        atomicAdd(&g_dis[d.x], v.x);
        atomicAdd(&g_dis[d.y], v.y);
        atomicAdd(&g_dis[d.z], v.z);
        atomicAdd(&g_dis[d.w], v.w);
    } else {
        for (int e = base; e < E; e++) atomicAdd(&g_dis[dst[e]], w[e]);
    }
}

__global__ void k_deg_fin(int n) {
    int i = blockIdx.x * blockDim.x + threadIdx.x;
    if (i < n) g_dis[i] = rsqrtf(g_dis[i]);
}

// 8 edges per thread: 16 independent L2 gathers in flight (latency-bound kernel)
__global__ void k_norm(const int* __restrict__ src, const int* __restrict__ dst,
                       const float* __restrict__ w, int E) {
    int q = blockIdx.x * blockDim.x + threadIdx.x;
    int base = q * 8;
    if (base + 7 < E) {
        int4   s0 = *(const int4*)&src[base];
        int4   s1 = *(const int4*)&src[base + 4];
        int4   d0 = *(const int4*)&dst[base];
        int4   d1 = *(const int4*)&dst[base + 4];
        float4 v0 = *(const float4*)&w[base];
        float4 v1 = *(const float4*)&w[base + 4];
        float a0 = g_dis[s0.x], a1 = g_dis[s0.y], a2 = g_dis[s0.z], a3 = g_dis[s0.w];
        float a4 = g_dis[s1.x], a5 = g_dis[s1.y], a6 = g_dis[s1.z], a7 = g_dis[s1.w];
        float b0 = g_dis[d0.x], b1 = g_dis[d0.y], b2 = g_dis[d0.z], b3 = g_dis[d0.w];
        float b4 = g_dis[d1.x], b5 = g_dis[d1.y], b6 = g_dis[d1.z], b7 = g_dis[d1.w];
        float4 o0 = make_float4(a0 * v0.x * b0, a1 * v0.y * b1, a2 * v0.z * b2, a3 * v0.w * b3);
        float4 o1 = make_float4(a4 * v1.x * b4, a5 * v1.y * b5, a6 * v1.z * b6, a7 * v1.w * b7);
        *(float4*)&g_norm[base]     = o0;
        *(float4*)&g_norm[base + 4] = o1;
    } else {
        for (int e = base; e < E; e++) g_norm[e] = g_dis[src[e]] * w[e] * g_dis[dst[e]];
    }
}

// ---------------- GEMM1 via mma.sync bf16 m16n8k16 (2-term split) ----------
// D[128,64] = A[128,512] * B[64,512]^T, fp32 accum.
// Split: A*B ~= Ahi*(Bhi + Blo); B exact to 2^-18, dropped Alo*B ~4e-5 rel.
// 256 threads = 8 warps as 4(m) x 2(n); warp tile 32x32 = 2x4 mma tiles of 16x8.
// Smem rows padded to 12 words: fragment pattern gid*12 + tig(+4) is
// bank-conflict-free (12g+t mod 32 distinct for g<8, t<8).
// Double-buffered: LDG(c+1) -> compute(c) -> STS(c+1), 1 syncthreads/chunk.
#define GM  128
#define NCH (INDIM / 16)           // 32 chunks of k=16

__device__ __forceinline__ void mma_bf16(float* c, const uint32_t* a, const uint32_t* b) {
    asm volatile(
        "mma.sync.aligned.m16n8k16.row.col.f32.bf16.bf16.f32 "
        "{%0,%1,%2,%3}, {%4,%5,%6,%7}, {%8,%9}, {%0,%1,%2,%3};"
        : "+f"(c[0]), "+f"(c[1]), "+f"(c[2]), "+f"(c[3])
        : "r"(a[0]), "r"(a[1]), "r"(a[2]), "r"(a[3]), "r"(b[0]), "r"(b[1]));
}

__global__ __launch_bounds__(256)
void k_gemm1_mma(const float* __restrict__ X, int Nrows) {
    __shared__ uint32_t Ah[2][GM][12];
    __shared__ uint32_t Bh[2][HID][12], Bl[2][HID][12];

    const int tid  = threadIdx.x;
    const int lane = tid & 31;
    const int wid  = tid >> 5;
    const int wm   = wid >> 1;          // 0..3
    const int wn   = wid & 1;           // 0..1
    const int gid  = lane >> 2;         // groupID
    const int tig  = lane & 3;          // threadID in group
    const int rowBase = blockIdx.x * GM;

    // staging geometry (chunk-independent)
    const int ra = tid >> 2;            // A row for p=0 (p=1: +64)
    const int kq = tid & 3;             // float4 slot within k16
    const int rb = tid >> 2;            // B row 0..63
    const int pg = tid & 3;             // B k-pair group (2 pairs each)

    float C[2][4][4];
    #pragma unroll
    for (int mt = 0; mt < 2; mt++)
        #pragma unroll
        for (int nt = 0; nt < 4; nt++)
            #pragma unroll
            for (int q = 0; q < 4; q++) C[mt][nt][q] = 0.0f;

    float4 va[2];
    uint2  vbh, vbl;

    // ---- prologue: load + stage chunk 0 ----
    #pragma unroll
    for (int p = 0; p < 2; p++) {
        int grow = rowBase + ra + p * 64;
        va[p] = make_float4(0.f, 0.f, 0.f, 0.f);
        if (grow < Nrows) va[p] = *(const float4*)&X[(size_t)grow * INDIM + kq * 4];
    }
    {
        size_t gi = (size_t)rb * (INDIM / 2) + pg * 2;
        vbh = *(const uint2*)&g_Wbhi[gi];
        vbl = *(const uint2*)&g_Wblo[gi];
    }
    #pragma unroll
    for (int p = 0; p < 2; p++) {
        uint32_t h0 = bf16x2(va[p].y, va[p].x);
        uint32_t h1 = bf16x2(va[p].w, va[p].z);
        *(uint2*)&Ah[0][ra + p * 64][kq * 2] = make_uint2(h0, h1);
    }
    *(uint2*)&Bh[0][rb][pg * 2] = vbh;
    *(uint2*)&Bl[0][rb][pg * 2] = vbl;
    __syncthreads();

    for (int c = 0; c < NCH; c++) {
        const int buf = c & 1;
        // ---- prefetch chunk c+1 into registers ----
        if (c + 1 < NCH) {
            const int k0n = (c + 1) * 16;
            #pragma unroll
            for (int p = 0; p < 2; p++) {
                int grow = rowBase + ra + p * 64;
                va[p] = make_float4(0.f, 0.f, 0.f, 0.f);
                if (grow < Nrows)
                    va[p] = *(const float4*)&X[(size_t)grow * INDIM + k0n + kq * 4];
            }
            size_t gi = (size_t)rb * (INDIM / 2) + (c + 1) * 8 + pg * 2;
            vbh = *(const uint2*)&g_Wbhi[gi];
            vbl = *(const uint2*)&g_Wblo[gi];
        }

        // ---- compute chunk c ----
        {
            const uint32_t (*pA)[12] = Ah[buf];
            const uint32_t (*pBh)[12] = Bh[buf];
            const uint32_t (*pBl)[12] = Bl[buf];
            uint32_t ah[2][4];
            #pragma unroll
            for (int mt = 0; mt < 2; mt++) {
                int r0 = wm * 32 + mt * 16 + gid;
                ah[mt][0] = pA[r0][tig];
                ah[mt][1] = pA[r0 + 8][tig];
                ah[mt][2] = pA[r0][tig + 4];
                ah[mt][3] = pA[r0 + 8][tig + 4];
            }
            uint32_t bhf[4][2], blf[4][2];
            #pragma unroll
            for (int nt = 0; nt < 4; nt++) {
                int cb = wn * 32 + nt * 8 + gid;
                bhf[nt][0] = pBh[cb][tig]; bhf[nt][1] = pBh[cb][tig + 4];
                blf[nt][0] = pBl[cb][tig]; blf[nt][1] = pBl[cb][tig + 4];
            }
            #pragma unroll
            for (int mt = 0; mt < 2; mt++)
                #pragma unroll
                for (int nt = 0; nt < 4; nt++) {
                    mma_bf16(C[mt][nt], ah[mt], bhf[nt]);
                    mma_bf16(C[mt][nt], ah[mt], blf[nt]);
                }
        }

        // ---- stage chunk c+1 ----
        if (c + 1 < NCH) {
            const int nb = buf ^ 1;
            #pragma unroll
            for (int p = 0; p < 2; p++) {
                uint32_t h0 = bf16x2(va[p].y, va[p].x);
                uint32_t h1 = bf16x2(va[p].w, va[p].z);
                *(uint2*)&Ah[nb][ra + p * 64][kq * 2] = make_uint2(h0, h1);
            }
            *(uint2*)&Bh[nb][rb][pg * 2] = vbh;
            *(uint2*)&Bl[nb][rb][pg * 2] = vbl;
        }
        __syncthreads();
    }

    // ---- epilogue: H and O1 = H * dis^2 (self-loop init) ----
    #pragma unroll
    for (int mt = 0; mt < 2; mt++) {
        int r0 = rowBase + wm * 32 + mt * 16 + gid;
        int r1 = r0 + 8;
        if (r0 < Nrows) {
            float d = g_dis[r0]; float sn = d * d;
            float* hrow = &g_H [(size_t)r0 * HID];
            float* orow = &g_O1[(size_t)r0 * HID];
            #pragma unroll
            for (int nt = 0; nt < 4; nt++) {
                int col = wn * 32 + nt * 8 + tig * 2;
                float2 v = make_float2(C[mt][nt][0], C[mt][nt][1]);
                *(float2*)&hrow[col] = v;
                *(float2*)&orow[col] = make_float2(v.x * sn, v.y * sn);
            }
        }
        if (r1 < Nrows) {
            float d = g_dis[r1]; float sn = d * d;
            float* hrow = &g_H [(size_t)r1 * HID];
            float* orow = &g_O1[(size_t)r1 * HID];
            #pragma unroll
            for (int nt = 0; nt < 4; nt++) {
                int col = wn * 32 + nt * 8 + tig * 2;
                float2 v = make_float2(C[mt][nt][2], C[mt][nt][3]);
                *(float2*)&hrow[col] = v;
                *(float2*)&orow[col] = make_float2(v.x * sn, v.y * sn);
            }
        }
    }
}

// ---------------- edge aggregation, 64 features (half-warp per edge) -------
__device__ __forceinline__ void red_add_v4(float* addr, float a, float b, float c, float d) {
    asm volatile("red.global.add.v4.f32 [%0], {%1, %2, %3, %4};"
                 :: "l"(addr), "f"(a), "f"(b), "f"(c), "f"(d) : "memory");
}

__global__ __launch_bounds__(256)
void k_agg64(const int* __restrict__ src, const int* __restrict__ dst, int E) {
    int t = blockIdx.x * blockDim.x + threadIdx.x;
    int e = t >> 4;
    if (e >= E) return;
    int lane = t & 15;
    int s = src[e];
    int d = dst[e];
    float nr = g_norm[e];
    float4 v = *(const float4*)&g_H[(size_t)s * HID + lane * 4];
    red_add_v4(&g_O1[(size_t)d * HID + lane * 4], v.x * nr, v.y * nr, v.z * nr, v.w * nr);
}

// ---------------- layer 2: H2 = relu(O1+b1) @ W2 ; O2 = H2 * selfnorm ------
__global__ __launch_bounds__(256)
void k_layer2(const float* __restrict__ b1, const float* __restrict__ W2, int Nn) {
    __shared__ float Ws[HID * NCLS];
    __shared__ float bs[HID];
    for (int i = threadIdx.x; i < HID * NCLS; i += blockDim.x) Ws[i] = W2[i];
    if (threadIdx.x < HID) bs[threadIdx.x] = b1[threadIdx.x];
    __syncthreads();

    int n = blockIdx.x * blockDim.x + threadIdx.x;
    if (n >= Nn) return;

    float acc[NCLS];
    #pragma unroll
    for (int c = 0; c < NCLS; c++) acc[c] = 0.0f;

    const float* row = &g_O1[(size_t)n * HID];
    #pragma unroll
    for (int jq = 0; jq < HID / 4; jq++) {
        float4 r = *(const float4*)&row[jq * 4];
        float tv[4];
        tv[0] = fmaxf(r.x + bs[jq * 4 + 0], 0.f);
        tv[1] = fmaxf(r.y + bs[jq * 4 + 1], 0.f);
        tv[2] = fmaxf(r.z + bs[jq * 4 + 2], 0.f);
        tv[3] = fmaxf(r.w + bs[jq * 4 + 3], 0.f);
        #pragma unroll
        for (int u = 0; u < 4; u++) {
            int j = jq * 4 + u;
            float tvu = tv[u];
            #pragma unroll
            for (int cq = 0; cq < 4; cq++) {
                float4 w = *(const float4*)&Ws[j * NCLS + cq * 4];
                acc[cq * 4 + 0] += tvu * w.x;
                acc[cq * 4 + 1] += tvu * w.y;
                acc[cq * 4 + 2] += tvu * w.z;
                acc[cq * 4 + 3] += tvu * w.w;
            }
        }
    }

    float d  = g_dis[n];
    float sn = d * d;
    #pragma unroll
    for (int cq = 0; cq < 4; cq++) {
        float4 v = make_float4(acc[cq*4+0], acc[cq*4+1], acc[cq*4+2], acc[cq*4+3]);
        *(float4*)&g_H2[(size_t)n * NCLS + cq * 4] = v;
        float4 o = make_float4(v.x * sn, v.y * sn, v.z * sn, v.w * sn);
        *(float4*)&g_O2[(size_t)n * NCLS + cq * 4] = o;
    }
}

// ---------------- edge aggregation, 16 features (4 lanes per edge) ---------
__global__ __launch_bounds__(256)
void k_agg16(const int* __restrict__ src, const int* __restrict__ dst, int E) {
    int t = blockIdx.x * blockDim.x + threadIdx.x;
    int e = t >> 2;
    if (e >= E) return;
    int lane = t & 3;
    int s = src[e];
    int d = dst[e];
    float nr = g_norm[e];
    float4 v = *(const float4*)&g_H2[(size_t)s * NCLS + lane * 4];
    red_add_v4(&g_O2[(size_t)d * NCLS + lane * 4], v.x * nr, v.y * nr, v.z * nr, v.w * nr);
}

// ---------------- final: out = log_softmax(O2 + b2) ------------------------
__global__ __launch_bounds__(256)
void k_lsm(const float* __restrict__ b2, float* __restrict__ out, int Nn) {
    __shared__ float bs[NCLS];
    if (threadIdx.x < NCLS) bs[threadIdx.x] = b2[threadIdx.x];
    __syncthreads();

    int n = blockIdx.x * blockDim.x + threadIdx.x;
    if (n >= Nn) return;

    float v[NCLS];
    #pragma unroll
    for (int cq = 0; cq < 4; cq++) {
        float4 r = *(const float4*)&g_O2[(size_t)n * NCLS + cq * 4];
        v[cq*4+0] = r.x + bs[cq*4+0];
        v[cq*4+1] = r.y + bs[cq*4+1];
        v[cq*4+2] = r.z + bs[cq*4+2];
        v[cq*4+3] = r.w + bs[cq*4+3];
    }
    float m = v[0];
    #pragma unroll
    for (int c = 1; c < NCLS; c++) m = fmaxf(m, v[c]);
    float s = 0.f;
    #pragma unroll
    for (int c = 0; c < NCLS; c++) s += expf(v[c] - m);
    float l = logf(s) + m;
    #pragma unroll
    for (int cq = 0; cq < 4; cq++) {
        float4 o = make_float4(v[cq*4+0]-l, v[cq*4+1]-l, v[cq*4+2]-l, v[cq*4+3]-l);
        *(float4*)&out[(size_t)n * NCLS + cq * 4] = o;
    }
}

// ---------------- launch ----------------------------------------------------
extern "C" void kernel_launch(void* const* d_in, const int* in_sizes, int n_in,
                              void* d_out, int out_size) {
    const float* x   = (const float*)d_in[0];   // [N, 512]
    const int*   ei  = (const int*)  d_in[1];   // [2, E]
    const float* ew  = (const float*)d_in[2];   // [E]
    const float* W1  = (const float*)d_in[3];   // [512, 64]
    const float* b1  = (const float*)d_in[4];   // [64]
    const float* W2  = (const float*)d_in[5];   // [64, 16]
    const float* b2  = (const float*)d_in[6];   // [16]
    float*       out = (float*)d_out;

    const int N = in_sizes[0] / INDIM;
    const int E = in_sizes[2];
    const int* src = ei;
    const int* dst = ei + E;

    const int T = 256;

    // 1: deg self-loop init + W1 bf16 hi/lo split (fused, independent ranges)
    k_prep<<<(N + T - 1) / T, T>>>(W1, N);
    // 2: weighted in-degree
    {
        int q = (E + 3) / 4;
        k_deg_acc<<<(q + T - 1) / T, T>>>(dst, ew, E);
    }
    // 3: deg -> rsqrt(deg)
    k_deg_fin<<<(N + T - 1) / T, T>>>(N);
    // 4: layer-1 GEMM (bf16 tensor pipe, 2-term split) — profiled slot
    k_gemm1_mma<<<(N + GM - 1) / GM, 256>>>(x, N);
    // 5: per-edge norm (independent of GEMM; needed only before agg64)
    {
        int q = (E + 7) / 8;
        k_norm<<<(q + T - 1) / T, T>>>(src, dst, ew, E);
    }
    // 6: layer-1 aggregation
    {
        long long th = (long long)E * 16;
        k_agg64<<<(int)((th + T - 1) / T), T>>>(src, dst, E);
    }
    // 7: layer 2 dense
    k_layer2<<<(N + T - 1) / T, T>>>(b1, W2, N);
    // 8: layer-2 aggregation
    {
        long long th = (long long)E * 4;
        k_agg16<<<(int)((th + T - 1) / T), T>>>(src, dst, E);
    }
    // 9: log-softmax epilogue
    k_lsm<<<(N + T - 1) / T, T>>>(b2, out, N);
}

// round 12
// speedup vs baseline: 1.5530x; 1.0553x over previous
#include <cuda_runtime.h>
#include <cstdint>

// Problem constants (fixed shapes for this problem instance).
#define NMAX   100000
#define EMAX   1600000
#define INDIM  512
#define HID    64
#define NCLS   16

// ---------------- scratch (device globals; no allocation allowed) ----------
__device__ __align__(256) float g_dis [NMAX];                    // deg -> rsqrt(deg)
__device__ __align__(256) float g_norm[EMAX];                    // per-edge norm
__device__ __align__(256) float g_H  [(size_t)NMAX * HID];       // x @ W1
__device__ __align__(256) float g_O1 [(size_t)NMAX * HID];       // aggregated layer-1
__device__ __align__(256) float g_H2 [(size_t)NMAX * NCLS];      // relu(O1+b1) @ W2
__device__ __align__(256) float g_O2 [(size_t)NMAX * NCLS];      // aggregated layer-2
// W1^T as packed bf16x2 over k-pairs: [n=0..63][kpair=0..255]
__device__ __align__(256) uint32_t g_Wbhi[(size_t)HID * INDIM / 2];

// pack two floats as bf16x2: result.lo = bf16(lo), result.hi = bf16(hi)
__device__ __forceinline__ uint32_t bf16x2(float hi, float lo) {
    uint32_t r;
    asm("cvt.rn.bf16x2.f32 %0, %1, %2;" : "=r"(r) : "f"(hi), "f"(lo));
    return r;
}

// ---------------- prep: deg init (self-loop) + W1 bf16 transpose/pack ------
__global__ void k_prep(const float* __restrict__ W1, int n) {
    int i = blockIdx.x * blockDim.x + threadIdx.x;
    if (i < n) g_dis[i] = 1.0f;                       // self-loop weight
    if (i < HID * INDIM / 2) {                        // W1^T bf16 packed
        int c  = i >> 8;                              // output column 0..63
        int kp = i & 255;                             // k-pair 0..255
        float v0 = W1[(size_t)(2 * kp)     * HID + c];
        float v1 = W1[(size_t)(2 * kp + 1) * HID + c];
        g_Wbhi[i] = bf16x2(v1, v0);
    }
}

__global__ void k_deg_acc(const int* __restrict__ dst, const float* __restrict__ w, int E) {
    int q = blockIdx.x * blockDim.x + threadIdx.x;
    int base = q * 4;
    if (base + 3 < E) {
        int4   d = *(const int4*)&dst[base];
        float4 v = *(const float4*)&w[base];
        atomicAdd(&g_dis[d.x], v.x);
        atomicAdd(&g_dis[d.y], v.y);
        atomicAdd(&g_dis[d.z], v.z);
        atomicAdd(&g_dis[d.w], v.w);
    } else {
        for (int e = base; e < E; e++) atomicAdd(&g_dis[dst[e]], w[e]);
    }
}

__global__ void k_deg_fin(int n) {
    int i = blockIdx.x * blockDim.x + threadIdx.x;
    if (i < n) g_dis[i] = rsqrtf(g_dis[i]);
}

// 8 edges per thread: 16 independent L2 gathers in flight (latency-bound kernel)
__global__ void k_norm(const int* __restrict__ src, const int* __restrict__ dst,
                       const float* __restrict__ w, int E) {
    int q = blockIdx.x * blockDim.x + threadIdx.x;
    int base = q * 8;
    if (base + 7 < E) {
        int4   s0 = *(const int4*)&src[base];
        int4   s1 = *(const int4*)&src[base + 4];
        int4   d0 = *(const int4*)&dst[base];
        int4   d1 = *(const int4*)&dst[base + 4];
        float4 v0 = *(const float4*)&w[base];
        float4 v1 = *(const float4*)&w[base + 4];
        float a0 = g_dis[s0.x], a1 = g_dis[s0.y], a2 = g_dis[s0.z], a3 = g_dis[s0.w];
        float a4 = g_dis[s1.x], a5 = g_dis[s1.y], a6 = g_dis[s1.z], a7 = g_dis[s1.w];
        float b0 = g_dis[d0.x], b1 = g_dis[d0.y], b2 = g_dis[d0.z], b3 = g_dis[d0.w];
        float b4 = g_dis[d1.x], b5 = g_dis[d1.y], b6 = g_dis[d1.z], b7 = g_dis[d1.w];
        float4 o0 = make_float4(a0 * v0.x * b0, a1 * v0.y * b1, a2 * v0.z * b2, a3 * v0.w * b3);
        float4 o1 = make_float4(a4 * v1.x * b4, a5 * v1.y * b5, a6 * v1.z * b6, a7 * v1.w * b7);
        *(float4*)&g_norm[base]     = o0;
        *(float4*)&g_norm[base + 4] = o1;
    } else {
        for (int e = base; e < E; e++) g_norm[e] = g_dis[src[e]] * w[e] * g_dis[dst[e]];
    }
}

// ---------------- GEMM1 via mma.sync bf16 m16n8k16 (1-term, pure bf16) -----
// D[128,64] = bf16(A)[128,512] * bf16(B)[64,512]^T, fp32 accum.
// A and B both rounded to bf16: two independent ~2^-9 rounding terms, each
// measured to contribute ~4e-5 end-to-end -> total ~7e-5, 12x under 1e-3.
// 256 threads = 8 warps as 4(m) x 2(n); warp tile 32x32 = 2x4 mma tiles of 16x8.
// Smem rows padded to 12 words: fragment pattern gid*12 + tig(+4) is
// bank-conflict-free (12g+t mod 32 distinct for g<8, t<8).
// Double-buffered: LDG(c+1) -> compute(c) -> STS(c+1), 1 syncthreads/chunk.
#define GM  128
#define NCH (INDIM / 16)           // 32 chunks of k=16

__device__ __forceinline__ void mma_bf16(float* c, const uint32_t* a, const uint32_t* b) {
    asm volatile(
        "mma.sync.aligned.m16n8k16.row.col.f32.bf16.bf16.f32 "
        "{%0,%1,%2,%3}, {%4,%5,%6,%7}, {%8,%9}, {%0,%1,%2,%3};"
        : "+f"(c[0]), "+f"(c[1]), "+f"(c[2]), "+f"(c[3])
        : "r"(a[0]), "r"(a[1]), "r"(a[2]), "r"(a[3]), "r"(b[0]), "r"(b[1]));
}

__global__ __launch_bounds__(256)
void k_gemm1_mma(const float* __restrict__ X, int Nrows) {
    __shared__ uint32_t Ah[2][GM][12];
    __shared__ uint32_t Bh[2][HID][12];

    const int tid  = threadIdx.x;
    const int lane = tid & 31;
    const int wid  = tid >> 5;
    const int wm   = wid >> 1;          // 0..3
    const int wn   = wid & 1;           // 0..1
    const int gid  = lane >> 2;         // groupID
    const int tig  = lane & 3;          // threadID in group
    const int rowBase = blockIdx.x * GM;

    // staging geometry (chunk-independent)
    const int ra = tid >> 2;            // A row for p=0 (p=1: +64)
    const int kq = tid & 3;             // float4 slot within k16
    const int rb = tid >> 2;            // B row 0..63
    const int pg = tid & 3;             // B k-pair group (2 pairs each)

    float C[2][4][4];
    #pragma unroll
    for (int mt = 0; mt < 2; mt++)
        #pragma unroll
        for (int nt = 0; nt < 4; nt++)
            #pragma unroll
            for (int q = 0; q < 4; q++) C[mt][nt][q] = 0.0f;

    float4 va[2];
    uint2  vbh;

    // ---- prologue: load + stage chunk 0 ----
    #pragma unroll
    for (int p = 0; p < 2; p++) {
        int grow = rowBase + ra + p * 64;
        va[p] = make_float4(0.f, 0.f, 0.f, 0.f);
        if (grow < Nrows) va[p] = *(const float4*)&X[(size_t)grow * INDIM + kq * 4];
    }
    vbh = *(const uint2*)&g_Wbhi[(size_t)rb * (INDIM / 2) + pg * 2];
    #pragma unroll
    for (int p = 0; p < 2; p++) {
        uint32_t h0 = bf16x2(va[p].y, va[p].x);
        uint32_t h1 = bf16x2(va[p].w, va[p].z);
        *(uint2*)&Ah[0][ra + p * 64][kq * 2] = make_uint2(h0, h1);
    }
    *(uint2*)&Bh[0][rb][pg * 2] = vbh;
    __syncthreads();

    for (int c = 0; c < NCH; c++) {
        const int buf = c & 1;
        // ---- prefetch chunk c+1 into registers ----
        if (c + 1 < NCH) {
            const int k0n = (c + 1) * 16;
            #pragma unroll
            for (int p = 0; p < 2; p++) {
                int grow = rowBase + ra + p * 64;
                va[p] = make_float4(0.f, 0.f, 0.f, 0.f);
                if (grow < Nrows)
                    va[p] = *(const float4*)&X[(size_t)grow * INDIM + k0n + kq * 4];
            }
            vbh = *(const uint2*)&g_Wbhi[(size_t)rb * (INDIM / 2) + (c + 1) * 8 + pg * 2];
        }

        // ---- compute chunk c ----
        {
            const uint32_t (*pA)[12] = Ah[buf];
            const uint32_t (*pBh)[12] = Bh[buf];
            uint32_t ah[2][4];
            #pragma unroll
            for (int mt = 0; mt < 2; mt++) {
                int r0 = wm * 32 + mt * 16 + gid;
                ah[mt][0] = pA[r0][tig];
                ah[mt][1] = pA[r0 + 8][tig];
                ah[mt][2] = pA[r0][tig + 4];
                ah[mt][3] = pA[r0 + 8][tig + 4];
            }
            uint32_t bhf[4][2];
            #pragma unroll
            for (int nt = 0; nt < 4; nt++) {
                int cb = wn * 32 + nt * 8 + gid;
                bhf[nt][0] = pBh[cb][tig]; bhf[nt][1] = pBh[cb][tig + 4];
            }
            #pragma unroll
            for (int mt = 0; mt < 2; mt++)
                #pragma unroll
                for (int nt = 0; nt < 4; nt++)
                    mma_bf16(C[mt][nt], ah[mt], bhf[nt]);
        }

        // ---- stage chunk c+1 ----
        if (c + 1 < NCH) {
            const int nb = buf ^ 1;
            #pragma unroll
            for (int p = 0; p < 2; p++) {
                uint32_t h0 = bf16x2(va[p].y, va[p].x);
                uint32_t h1 = bf16x2(va[p].w, va[p].z);
                *(uint2*)&Ah[nb][ra + p * 64][kq * 2] = make_uint2(h0, h1);
            }
            *(uint2*)&Bh[nb][rb][pg * 2] = vbh;
        }
        __syncthreads();
    }

    // ---- epilogue: H and O1 = H * dis^2 (self-loop init) ----
    #pragma unroll
    for (int mt = 0; mt < 2; mt++) {
        int r0 = rowBase + wm * 32 + mt * 16 + gid;
        int r1 = r0 + 8;
        if (r0 < Nrows) {
            float d = g_dis[r0]; float sn = d * d;
            float* hrow = &g_H [(size_t)r0 * HID];
            float* orow = &g_O1[(size_t)r0 * HID];
            #pragma unroll
            for (int nt = 0; nt < 4; nt++) {
                int col = wn * 32 + nt * 8 + tig * 2;
                float2 v = make_float2(C[mt][nt][0], C[mt][nt][1]);
                *(float2*)&hrow[col] = v;
                *(float2*)&orow[col] = make_float2(v.x * sn, v.y * sn);
            }
        }
        if (r1 < Nrows) {
            float d = g_dis[r1]; float sn = d * d;
            float* hrow = &g_H [(size_t)r1 * HID];
            float* orow = &g_O1[(size_t)r1 * HID];
            #pragma unroll
            for (int nt = 0; nt < 4; nt++) {
                int col = wn * 32 + nt * 8 + tig * 2;
                float2 v = make_float2(C[mt][nt][2], C[mt][nt][3]);
                *(float2*)&hrow[col] = v;
                *(float2*)&orow[col] = make_float2(v.x * sn, v.y * sn);
            }
        }
    }
}

// ---------------- edge aggregation, 64 features (half-warp per edge) -------
__device__ __forceinline__ void red_add_v4(float* addr, float a, float b, float c, float d) {
    asm volatile("red.global.add.v4.f32 [%0], {%1, %2, %3, %4};"
                 :: "l"(addr), "f"(a), "f"(b), "f"(c), "f"(d) : "memory");
}

__global__ __launch_bounds__(256)
void k_agg64(const int* __restrict__ src, const int* __restrict__ dst, int E) {
    int t = blockIdx.x * blockDim.x + threadIdx.x;
    int e = t >> 4;
    if (e >= E) return;
    int lane = t & 15;
    int s = src[e];
    int d = dst[e];
    float nr = g_norm[e];
    float4 v = *(const float4*)&g_H[(size_t)s * HID + lane * 4];
    red_add_v4(&g_O1[(size_t)d * HID + lane * 4], v.x * nr, v.y * nr, v.z * nr, v.w * nr);
}

// ---------------- layer 2: H2 = relu(O1+b1) @ W2 ; O2 = H2 * selfnorm ------
__global__ __launch_bounds__(256)
void k_layer2(const float* __restrict__ b1, const float* __restrict__ W2, int Nn) {
    __shared__ float Ws[HID * NCLS];
    __shared__ float bs[HID];
    for (int i = threadIdx.x; i < HID * NCLS; i += blockDim.x) Ws[i] = W2[i];
    if (threadIdx.x < HID) bs[threadIdx.x] = b1[threadIdx.x];
    __syncthreads();

    int n = blockIdx.x * blockDim.x + threadIdx.x;
    if (n >= Nn) return;

    float acc[NCLS];
    #pragma unroll
    for (int c = 0; c < NCLS; c++) acc[c] = 0.0f;

    const float* row = &g_O1[(size_t)n * HID];
    #pragma unroll
    for (int jq = 0; jq < HID / 4; jq++) {
        float4 r = *(const float4*)&row[jq * 4];
        float tv[4];
        tv[0] = fmaxf(r.x + bs[jq * 4 + 0], 0.f);
        tv[1] = fmaxf(r.y + bs[jq * 4 + 1], 0.f);
        tv[2] = fmaxf(r.z + bs[jq * 4 + 2], 0.f);
        tv[3] = fmaxf(r.w + bs[jq * 4 + 3], 0.f);
        #pragma unroll
        for (int u = 0; u < 4; u++) {
            int j = jq * 4 + u;
            float tvu = tv[u];
            #pragma unroll
            for (int cq = 0; cq < 4; cq++) {
                float4 w = *(const float4*)&Ws[j * NCLS + cq * 4];
                acc[cq * 4 + 0] += tvu * w.x;
                acc[cq * 4 + 1] += tvu * w.y;
                acc[cq * 4 + 2] += tvu * w.z;
                acc[cq * 4 + 3] += tvu * w.w;
            }
        }
    }

    float d  = g_dis[n];
    float sn = d * d;
    #pragma unroll
    for (int cq = 0; cq < 4; cq++) {
        float4 v = make_float4(acc[cq*4+0], acc[cq*4+1], acc[cq*4+2], acc[cq*4+3]);
        *(float4*)&g_H2[(size_t)n * NCLS + cq * 4] = v;
        float4 o = make_float4(v.x * sn, v.y * sn, v.z * sn, v.w * sn);
        *(float4*)&g_O2[(size_t)n * NCLS + cq * 4] = o;
    }
}

// ---------------- edge aggregation, 16 features (4 lanes per edge) ---------
__global__ __launch_bounds__(256)
void k_agg16(const int* __restrict__ src, const int* __restrict__ dst, int E) {
    int t = blockIdx.x * blockDim.x + threadIdx.x;
    int e = t >> 2;
    if (e >= E) return;
    int lane = t & 3;
    int s = src[e];
    int d = dst[e];
    float nr = g_norm[e];
    float4 v = *(const float4*)&g_H2[(size_t)s * NCLS + lane * 4];
    red_add_v4(&g_O2[(size_t)d * NCLS + lane * 4], v.x * nr, v.y * nr, v.z * nr, v.w * nr);
}

// ---------------- final: out = log_softmax(O2 + b2) ------------------------
__global__ __launch_bounds__(256)
void k_lsm(const float* __restrict__ b2, float* __restrict__ out, int Nn) {
    __shared__ float bs[NCLS];
    if (threadIdx.x < NCLS) bs[threadIdx.x] = b2[threadIdx.x];
    __syncthreads();

    int n = blockIdx.x * blockDim.x + threadIdx.x;
    if (n >= Nn) return;

    float v[NCLS];
    #pragma unroll
    for (int cq = 0; cq < 4; cq++) {
        float4 r = *(const float4*)&g_O2[(size_t)n * NCLS + cq * 4];
        v[cq*4+0] = r.x + bs[cq*4+0];
        v[cq*4+1] = r.y + bs[cq*4+1];
        v[cq*4+2] = r.z + bs[cq*4+2];
        v[cq*4+3] = r.w + bs[cq*4+3];
    }
    float m = v[0];
    #pragma unroll
    for (int c = 1; c < NCLS; c++) m = fmaxf(m, v[c]);
    float s = 0.f;
    #pragma unroll
    for (int c = 0; c < NCLS; c++) s += expf(v[c] - m);
    float l = logf(s) + m;
    #pragma unroll
    for (int cq = 0; cq < 4; cq++) {
        float4 o = make_float4(v[cq*4+0]-l, v[cq*4+1]-l, v[cq*4+2]-l, v[cq*4+3]-l);
        *(float4*)&out[(size_t)n * NCLS + cq * 4] = o;
    }
}

// ---------------- launch ----------------------------------------------------
extern "C" void kernel_launch(void* const* d_in, const int* in_sizes, int n_in,
                              void* d_out, int out_size) {
    const float* x   = (const float*)d_in[0];   // [N, 512]
    const int*   ei  = (const int*)  d_in[1];   // [2, E]
    const float* ew  = (const float*)d_in[2];   // [E]
    const float* W1  = (const float*)d_in[3];   // [512, 64]
    const float* b1  = (const float*)d_in[4];   // [64]
    const float* W2  = (const float*)d_in[5];   // [64, 16]
    const float* b2  = (const float*)d_in[6];   // [16]
    float*       out = (float*)d_out;

    const int N = in_sizes[0] / INDIM;
    const int E = in_sizes[2];
    const int* src = ei;
    const int* dst = ei + E;

    const int T = 256;

    // 1: deg self-loop init + W1 bf16 transpose/pack (fused, independent ranges)
    k_prep<<<(N + T - 1) / T, T>>>(W1, N);
    // 2: weighted in-degree
    {
        int q = (E + 3) / 4;
        k_deg_acc<<<(q + T - 1) / T, T>>>(dst, ew, E);
    }
    // 3: deg -> rsqrt(deg)
    k_deg_fin<<<(N + T - 1) / T, T>>>(N);
    // 4: layer-1 GEMM (bf16 tensor pipe, 1-term) — profiled slot
    k_gemm1_mma<<<(N + GM - 1) / GM, 256>>>(x, N);
    // 5: per-edge norm (independent of GEMM; needed only before agg64)
    {
        int q = (E + 7) / 8;
        k_norm<<<(q + T - 1) / T, T>>>(src, dst, ew, E);
    }
    // 6: layer-1 aggregation
    {
        long long th = (long long)E * 16;
        k_agg64<<<(int)((th + T - 1) / T), T>>>(src, dst, E);
    }
    // 7: layer 2 dense
    k_layer2<<<(N + T - 1) / T, T>>>(b1, W2, N);
    // 8: layer-2 aggregation
    {
        long long th = (long long)E * 4;
        k_agg16<<<(int)((th + T - 1) / T), T>>>(src, dst, E);
    }
    // 9: log-softmax epilogue
    k_lsm<<<(N + T - 1) / T, T>>>(b2, out, N);
}